// round 10
// baseline (speedup 1.0000x reference)
#include <cuda_runtime.h>
#include <cuda_fp16.h>
#include <math.h>

// ---------------- problem dims ----------------
#define BB    64
#define NN    1024
#define H16   256
#define H64   1024
#define H128  2048
#define NGATE 8192

#define NCTA_MAX 148
#define WROWS 55                                 // gate rows resident in SMEM per CTA
// dynamic SMEM layout for lstm kernel
#define OFF_H16   (WROWS * 2048 * 2)             // 225280: fp16 h copy (4096 B)
#define OFF_G     (OFF_H16 + H128 * 2)           // gate preacts  (256 B)
#define OFF_C     (OFF_G + 64 * 4)               // cell state    (64 B)
#define LSTM_SMEM (OFF_C + 64)                   // 229696 B (<= 232448 max)

// ---------------- device scratch ----------------
__device__ __align__(16) float  g_x [BB * NN];
__device__ __align__(16) float  g_af[BB * H16];
__device__ __align__(16) float  g_ai[BB * H64];
__device__ __align__(16) float  g_z [BB * H128];
__device__ __align__(16) __half g_z16[BB * H128];
__device__ __align__(16) float  g_gi[BB * NGATE];
__device__ __align__(16) float  g_part[1 << 21];     // split-K partials (8MB)
__device__ __align__(16) __half g_h16[2][H128];      // fp16 recurrent h (double-buffered)
__device__ unsigned g_slot[NCTA_MAX * 8];            // spread barrier slots (32B apart)

__global__ void reset_kernel() {
    for (int i = threadIdx.x; i < NCTA_MAX * 8; i += blockDim.x) g_slot[i] = 0u;
}

// ---------------- release/acquire helpers ----------------
__device__ __forceinline__ void st_release(unsigned* p, unsigned v) {
    asm volatile("st.release.gpu.global.u32 [%0], %1;" :: "l"(p), "r"(v) : "memory");
}
__device__ __forceinline__ unsigned ld_acquire(const unsigned* p) {
    unsigned v;
    asm volatile("ld.acquire.gpu.global.u32 %0, [%1];" : "=r"(v) : "l"(p) : "memory");
    return v;
}

// ---------------- GCN: one block per sample ----------------
__global__ __launch_bounds__(1024) void gcn_kernel(
    const float* __restrict__ inp,
    const float* __restrict__ gc1w, const float* __restrict__ gc1b,
    const float* __restrict__ gc2w, const float* __restrict__ gc2b)
{
    __shared__ float xs[NN];
    __shared__ float s2[NN];
    const int s = blockIdx.x;
    const int i = threadIdx.x;
    xs[i] = inp[s * NN + i];
    __syncthreads();
    const float xi = xs[i];

    float d0 = INFINITY, d1 = INFINITY, d2 = INFINITY, d3 = INFINITY;
    int i0 = 0, i1 = 0, i2 = 0, i3 = 0;
#pragma unroll 4
    for (int j = 0; j < NN; ++j) {
        float dj = fabsf(xi - xs[j]);
        if (j != i && dj < d3) {
            if (dj < d2) {
                d3 = d2; i3 = i2;
                if (dj < d1) {
                    d2 = d1; i2 = i1;
                    if (dj < d0) { d1 = d0; i1 = i0; d0 = dj; i0 = j; }
                    else         { d1 = dj; i1 = j; }
                } else { d2 = dj; i2 = j; }
            } else { d3 = dj; i3 = j; }
        }
    }

    float S = xs[i0] + xs[i1] + xs[i2] + xs[i3];
    float v = 0.f;
#pragma unroll
    for (int c = 0; c < 4; ++c) {
        float hc = fmaxf(gc1w[c] * S + gc1b[c], 0.f);
        v += hc * gc2w[c];
    }
    s2[i] = v;
    __syncthreads();
    g_x[s * NN + i] = s2[i0] + s2[i1] + s2[i2] + s2[i3] + gc2b[0];
}

// ---------------- small split-K GEMM (64xR', 128 thr) for fl/il ----------------
template <int R, int J, int KC>
__global__ __launch_bounds__(128) void gemm_sk(
    const float* __restrict__ A, const float* __restrict__ W, float* __restrict__ part)
{
    __shared__ float As[64][33];
    __shared__ float Ws[32][33];
    const int JC  = J / KC;
    const int kc  = blockIdx.y;
    const int br0 = blockIdx.x * 32;
    const int tid = threadIdx.x;
    const int tq  = tid & 15;
    const int rq  = tid >> 4;

    float acc[4][4];
#pragma unroll
    for (int a = 0; a < 4; ++a)
#pragma unroll
        for (int b = 0; b < 4; ++b) acc[a][b] = 0.f;

    const int j_end = (kc + 1) * JC;
    for (int j0 = kc * JC; j0 < j_end; j0 += 32) {
        for (int idx = tid; idx < 64 * 32; idx += 128) {
            int row = idx >> 5, col = idx & 31;
            As[row][col] = A[row * J + j0 + col];
        }
        for (int idx = tid; idx < 32 * 32; idx += 128) {
            int row = idx >> 5, col = idx & 31;
            Ws[row][col] = W[(size_t)(br0 + row) * J + j0 + col];
        }
        __syncthreads();
#pragma unroll
        for (int kk = 0; kk < 32; ++kk) {
            float av[4], wv[4];
#pragma unroll
            for (int a = 0; a < 4; ++a) av[a] = As[tq + 16 * a][kk];
#pragma unroll
            for (int b = 0; b < 4; ++b) wv[b] = Ws[rq + 8 * b][kk];
#pragma unroll
            for (int a = 0; a < 4; ++a)
#pragma unroll
                for (int b = 0; b < 4; ++b) acc[a][b] += av[a] * wv[b];
        }
        __syncthreads();
    }
#pragma unroll
    for (int a = 0; a < 4; ++a)
#pragma unroll
        for (int b = 0; b < 4; ++b)
            part[(size_t)kc * 64 * R + (tq + 16 * a) * R + br0 + rq + 8 * b] = acc[a][b];
}

// ---------------- big split-K fp32 GEMM (ol layer): 64x64 tile, double-buffered ----------------
template <int R, int J, int KC>
__global__ __launch_bounds__(256) void gemm64(
    const float* __restrict__ A, const float* __restrict__ W, float* __restrict__ part)
{
    __shared__ float As[2][64][33];
    __shared__ float Ws[2][64][33];
    const int JC  = J / KC;
    const int kc  = blockIdx.y;
    const int br0 = blockIdx.x * 64;
    const int tid = threadIdx.x;
    const int tq  = tid & 15;
    const int rq  = tid >> 4;

    float acc[4][4];
#pragma unroll
    for (int a = 0; a < 4; ++a)
#pragma unroll
        for (int b = 0; b < 4; ++b) acc[a][b] = 0.f;

    const int jbeg = kc * JC;
    const int nit  = JC / 32;

    auto load = [&](int s, int j0) {
#pragma unroll
        for (int idx = tid; idx < 64 * 32; idx += 256) {
            int row = idx >> 5, col = idx & 31;
            As[s][row][col] = A[row * J + j0 + col];
            Ws[s][row][col] = W[(size_t)(br0 + row) * J + j0 + col];
        }
    };

    load(0, jbeg);
    __syncthreads();
    for (int it = 0; it < nit; ++it) {
        int s = it & 1;
        if (it + 1 < nit) load(s ^ 1, jbeg + (it + 1) * 32);
#pragma unroll
        for (int kk = 0; kk < 32; ++kk) {
            float av[4], wv[4];
#pragma unroll
            for (int a = 0; a < 4; ++a) av[a] = As[s][tq + 16 * a][kk];
#pragma unroll
            for (int b = 0; b < 4; ++b) wv[b] = Ws[s][rq + 16 * b][kk];
#pragma unroll
            for (int a = 0; a < 4; ++a)
#pragma unroll
                for (int b = 0; b < 4; ++b) acc[a][b] += av[a] * wv[b];
        }
        __syncthreads();
    }
#pragma unroll
    for (int a = 0; a < 4; ++a)
#pragma unroll
        for (int b = 0; b < 4; ++b)
            part[(size_t)kc * 64 * R + (tq + 16 * a) * R + br0 + rq + 16 * b] = acc[a][b];
}

// ---------------- z fp32 -> fp16 ----------------
__global__ __launch_bounds__(256) void convert_z()
{
    int i = blockIdx.x * 256 + threadIdx.x;          // half2 index, 64*2048/2 = 65536
    if (i >= BB * H128 / 2) return;
    float2 v = ((const float2*)g_z)[i];
    ((__half2*)g_z16)[i] = __floats2half2_rn(v.x, v.y);
}

// ---------------- gate GEMM: fp16 HFMA2, KC=1, fused bias epilogue ----------------
// C[t][r] = sum_j z16[t][j]*w_ih16[r][j] + b1[r] + b2[r]; W converted fp32->fp16 in-load.
template <int R, int J>
__global__ __launch_bounds__(256) void gemm64h_f(
    const __half* __restrict__ A16, const float* __restrict__ W,
    const float* __restrict__ b1, const float* __restrict__ b2,
    float* __restrict__ C)
{
    __shared__ __half2 As[2][64][17];   // 16 half2 (=32 K) + 1 pad
    __shared__ __half2 Ws[2][64][17];
    const int br0 = blockIdx.x * 64;
    const int tid = threadIdx.x;
    const int tq  = tid & 15;
    const int rq  = tid >> 4;
    const int nit = J / 32;
    const int row = tid >> 2;           // 0..63
    const int c4  = tid & 3;            // 16B chunk within 32-half row slice

    float acc[4][4];
#pragma unroll
    for (int a = 0; a < 4; ++a)
#pragma unroll
        for (int b = 0; b < 4; ++b) acc[a][b] = 0.f;

    auto load = [&](int s, int j0) {
        {
            uint4 v = *((const uint4*)(A16 + row * J + j0) + c4);
            const __half2* pv = (const __half2*)&v;
            __half2* d = &As[s][row][c4 * 4];
            d[0] = pv[0]; d[1] = pv[1]; d[2] = pv[2]; d[3] = pv[3];
        }
        {
            const float4* src = (const float4*)(W + (size_t)(br0 + row) * J + j0) + c4 * 2;
            float4 a = src[0], b = src[1];
            __half2* d = &Ws[s][row][c4 * 4];
            d[0] = __floats2half2_rn(a.x, a.y);
            d[1] = __floats2half2_rn(a.z, a.w);
            d[2] = __floats2half2_rn(b.x, b.y);
            d[3] = __floats2half2_rn(b.z, b.w);
        }
    };

    load(0, 0);
    __syncthreads();
    for (int it = 0; it < nit; ++it) {
        int s = it & 1;
        if (it + 1 < nit) load(s ^ 1, (it + 1) * 32);
        __half2 h2[4][4];
        {
            __half2 av[4], wv[4];
#pragma unroll
            for (int a = 0; a < 4; ++a) av[a] = As[s][tq + 16 * a][0];
#pragma unroll
            for (int b = 0; b < 4; ++b) wv[b] = Ws[s][rq + 16 * b][0];
#pragma unroll
            for (int a = 0; a < 4; ++a)
#pragma unroll
                for (int b = 0; b < 4; ++b) h2[a][b] = __hmul2(av[a], wv[b]);
        }
#pragma unroll
        for (int kk = 1; kk < 16; ++kk) {
            __half2 av[4], wv[4];
#pragma unroll
            for (int a = 0; a < 4; ++a) av[a] = As[s][tq + 16 * a][kk];
#pragma unroll
            for (int b = 0; b < 4; ++b) wv[b] = Ws[s][rq + 16 * b][kk];
#pragma unroll
            for (int a = 0; a < 4; ++a)
#pragma unroll
                for (int b = 0; b < 4; ++b) h2[a][b] = __hfma2(av[a], wv[b], h2[a][b]);
        }
#pragma unroll
        for (int a = 0; a < 4; ++a)
#pragma unroll
            for (int b = 0; b < 4; ++b) {
                float2 f = __half22float2(h2[a][b]);
                acc[a][b] += f.x + f.y;
            }
        __syncthreads();
    }
#pragma unroll
    for (int b = 0; b < 4; ++b) {
        int r = br0 + rq + 16 * b;
        float bias = b1[r] + b2[r];
#pragma unroll
        for (int a = 0; a < 4; ++a)
            C[(tq + 16 * a) * R + r] = acc[a][b] + bias;
    }
}

// ---------------- reduce partials ----------------
template <int R, int KC, bool RELU>
__global__ __launch_bounds__(256) void reduce_k(
    const float* __restrict__ part, const float* __restrict__ b1,
    float* __restrict__ C)
{
    int i = blockIdx.x * 256 + threadIdx.x;
    if (i >= 64 * R) return;
    int r = i % R;
    float s = 0.f;
#pragma unroll
    for (int kc = 0; kc < KC; ++kc) s += part[(size_t)kc * 64 * R + i];
    s += b1[r];
    if (RELU) s = fmaxf(s, 0.f);
    C[i] = s;
}

__device__ __forceinline__ float sigmoidf_(float x) { return 1.f / (1.f + expf(-x)); }

// ---------------- persistent LSTM: 55 SMEM rows, split-chain HFMA2, lean sync ----------------
__global__ __launch_bounds__(1024, 1) void lstm_kernel(
    const float* __restrict__ w_hh, float* __restrict__ out, int ncta)
{
    extern __shared__ unsigned char sm[];
    __half* w_sm = (__half*)sm;                     // [WROWS][2048] fp16, row = lr
    __half* h16  = (__half*)(sm + OFF_H16);         // [2048]
    float*  gsm  = (float*)(sm + OFF_G);            // [64]
    float*  csm  = (float*)(sm + OFF_C);            // [16]

    const int tid  = threadIdx.x;
    const int bid  = blockIdx.x;
    const int warp = tid >> 5, lane = tid & 31;

    const int base = H128 / ncta;
    const int rem  = H128 - base * ncta;
    const int nu   = (bid < rem) ? base + 1 : base;
    const int u0   = bid * base + min(bid, rem);
    const int nrows = 4 * nu;
    const int wrows = (nrows < WROWS) ? nrows : WROWS;   // rows resident in SMEM

    // prologue: convert resident rows fp32 -> fp16, SMEM row index = lr
    {
        const int tot2 = wrows * 1024;              // half2 count
        __half2* dst = (__half2*)w_sm;
        for (int idx = tid; idx < tot2; idx += 1024) {
            int lr = idx >> 10, c2 = idx & 1023;
            int g = lr / nu, ui = lr - g * nu;
            const float2* src = (const float2*)(w_hh + (size_t)(g * H128 + u0 + ui) * H128);
            float2 v = src[c2];
            dst[idx] = __floats2half2_rn(v.x, v.y);
        }
    }

    // per-warp row assignment: lr = warp + 32*k (cnt uniform per warp)
    int cnt = 0;
    int rowg[2], gsl[2];
    bool insm[2];
    const uint4*  wr16[2];
    const float4* wr32[2];
#pragma unroll
    for (int k = 0; k < 2; ++k) {
        int lr = warp + 32 * k;
        if (lr < nrows) {
            int g = lr / nu, ui = lr - g * nu;
            rowg[cnt] = g * H128 + u0 + ui;
            gsl [cnt] = lr;
            insm[cnt] = (lr < wrows);
            wr16[cnt] = (const uint4*)(w_sm + (size_t)lr * H128);
            wr32[cnt] = (const float4*)(w_hh + (size_t)rowg[cnt] * H128);
            ++cnt;
        }
    }

    if (tid < nu) { csm[tid] = 0.f; g_h16[0][u0 + tid] = __float2half(0.f); }
    __syncthreads();
    if (tid == 0) st_release(&g_slot[bid * 8], 1u);
    if (tid < ncta) { while (ld_acquire(&g_slot[tid * 8]) < 1u) {} }
    __syncthreads();

    for (int t = 0; t < BB; ++t) {
        // broadcast h into SMEM (already fp16 in global)
        if (tid < H128 / 8) {
            uint4 v = __ldcg((const uint4*)g_h16[t & 1] + tid);
            ((uint4*)h16)[tid] = v;
        }
        // prefetch gate-input terms (L2-resident)
        float gi[2] = {0.f, 0.f};
        if (lane == 0) {
#pragma unroll
            for (int k = 0; k < 2; ++k)
                if (k < cnt) gi[k] = g_gi[t * NGATE + rowg[k]];
        }
        __syncthreads();

        float acc[2] = {0.f, 0.f};
        const uint4* h16u = (const uint4*)h16;
#pragma unroll
        for (int ii = 0; ii < 4; ++ii) {
            const int o = lane + 64 * ii;
            uint4 ha = h16u[o], hb = h16u[o + 32];
            const __half2* hpa = (const __half2*)&ha;
            const __half2* hpb = (const __half2*)&hb;
#pragma unroll
            for (int k = 0; k < 2; ++k) {
                if (k >= cnt) break;                 // warp-uniform branch
                __half2 sa, sb;                      // two independent chains (ILP)
                if (insm[k]) {
                    uint4 wa = wr16[k][o], wb = wr16[k][o + 32];
                    const __half2* wpa = (const __half2*)&wa;
                    const __half2* wpb = (const __half2*)&wb;
                    sa = __hmul2(wpa[0], hpa[0]);
                    sb = __hmul2(wpb[0], hpb[0]);
                    sa = __hfma2(wpa[1], hpa[1], sa);
                    sb = __hfma2(wpb[1], hpb[1], sb);
                    sa = __hfma2(wpa[2], hpa[2], sa);
                    sb = __hfma2(wpb[2], hpb[2], sb);
                    sa = __hfma2(wpa[3], hpa[3], sa);
                    sb = __hfma2(wpb[3], hpb[3], sb);
                } else {
                    float4 a0 = __ldg(wr32[k] + 2 * o);
                    float4 a1 = __ldg(wr32[k] + 2 * o + 1);
                    float4 b0 = __ldg(wr32[k] + 2 * (o + 32));
                    float4 b1 = __ldg(wr32[k] + 2 * (o + 32) + 1);
                    sa = __hmul2(__floats2half2_rn(a0.x, a0.y), hpa[0]);
                    sb = __hmul2(__floats2half2_rn(b0.x, b0.y), hpb[0]);
                    sa = __hfma2(__floats2half2_rn(a0.z, a0.w), hpa[1], sa);
                    sb = __hfma2(__floats2half2_rn(b0.z, b0.w), hpb[1], sb);
                    sa = __hfma2(__floats2half2_rn(a1.x, a1.y), hpa[2], sa);
                    sb = __hfma2(__floats2half2_rn(b1.x, b1.y), hpb[2], sb);
                    sa = __hfma2(__floats2half2_rn(a1.z, a1.w), hpa[3], sa);
                    sb = __hfma2(__floats2half2_rn(b1.z, b1.w), hpb[3], sb);
                }
                float2 fa = __half22float2(sa);
                float2 fb = __half22float2(sb);
                acc[k] += (fa.x + fa.y) + (fb.x + fb.y);
            }
        }
#pragma unroll
        for (int k = 0; k < 2; ++k)
#pragma unroll
            for (int o = 16; o > 0; o >>= 1) acc[k] += __shfl_xor_sync(0xffffffffu, acc[k], o);
        if (lane == 0) {
#pragma unroll
            for (int k = 0; k < 2; ++k)
                if (k < cnt) gsm[gsl[k]] = acc[k] + gi[k];
        }
        __syncthreads();

        // warp 0: activation epilogue + h publish + release (no extra CTA barrier)
        if (warp == 0) {
            if (tid < nu) {
                float ig = gsm[tid], fg = gsm[nu + tid], gg = gsm[2 * nu + tid], og = gsm[3 * nu + tid];
                float c = sigmoidf_(fg) * csm[tid] + sigmoidf_(ig) * tanhf(gg);
                float h = sigmoidf_(og) * tanhf(c);
                csm[tid] = c;
                g_h16[(t + 1) & 1][u0 + tid] = __float2half(h);
                out[t * H128 + u0 + tid] = h;
            }
            __syncwarp();
            if (tid == 0) st_release(&g_slot[bid * 8], (unsigned)(t + 2));
        }
        if (tid < ncta) { unsigned tgt = (unsigned)(t + 2); while (ld_acquire(&g_slot[tid * 8]) < tgt) {} }
        __syncthreads();
    }
}

// ---------------- launch ----------------
extern "C" void kernel_launch(void* const* d_in, const int* in_sizes, int n_in,
                              void* d_out, int out_size)
{
    const float* inp  = (const float*)d_in[0];
    const float* gc1w = (const float*)d_in[3];
    const float* gc1b = (const float*)d_in[4];
    const float* gc2w = (const float*)d_in[5];
    const float* gc2b = (const float*)d_in[6];
    const float* flw  = (const float*)d_in[7];
    const float* flb  = (const float*)d_in[8];
    const float* ilw  = (const float*)d_in[9];
    const float* ilb  = (const float*)d_in[10];
    const float* olw  = (const float*)d_in[11];
    const float* olb  = (const float*)d_in[12];
    const float* wih  = (const float*)d_in[13];
    const float* whh  = (const float*)d_in[14];
    const float* bih  = (const float*)d_in[15];
    const float* bhh  = (const float*)d_in[16];
    float* out = (float*)d_out;

    void *px, *paf, *pai, *pz, *pz16, *pgi, *ppart;
    cudaGetSymbolAddress(&px,    g_x);
    cudaGetSymbolAddress(&paf,   g_af);
    cudaGetSymbolAddress(&pai,   g_ai);
    cudaGetSymbolAddress(&pz,    g_z);
    cudaGetSymbolAddress(&pz16,  g_z16);
    cudaGetSymbolAddress(&pgi,   g_gi);
    cudaGetSymbolAddress(&ppart, g_part);
    float* part = (float*)ppart;

    int sms = 0;
    cudaDeviceGetAttribute(&sms, cudaDevAttrMultiProcessorCount, 0);
    int ncta = sms;
    if (ncta > NCTA_MAX) ncta = NCTA_MAX;
    if (ncta < 128) ncta = 128;

    cudaFuncSetAttribute(lstm_kernel, cudaFuncAttributeMaxDynamicSharedMemorySize, LSTM_SMEM);

    reset_kernel<<<1, 256>>>();
    gcn_kernel<<<BB, NN>>>(inp, gc1w, gc1b, gc2w, gc2b);

    // fl: [64,256] = x @ fl_w.T ; relu
    gemm_sk<H16, NN, 16><<<dim3(H16 / 32, 16), 128>>>((const float*)px, flw, part);
    reduce_k<H16, 16, true><<<(64 * H16 + 255) / 256, 256>>>(part, flb, (float*)paf);
    // il: [64,1024] = af @ il_w.T ; relu
    gemm_sk<H64, H16, 4><<<dim3(H64 / 32, 4), 128>>>((const float*)paf, ilw, part);
    reduce_k<H64, 4, true><<<(64 * H64 + 255) / 256, 256>>>(part, ilb, (float*)pai);
    // ol: [64,2048] = ai @ ol_w.T ; relu -> z
    gemm64<H128, H64, 4><<<dim3(H128 / 64, 4), 256>>>((const float*)pai, olw, part);
    reduce_k<H128, 4, true><<<(64 * H128 + 255) / 256, 256>>>(part, olb, (float*)pz);
    // z -> fp16
    convert_z<<<(BB * H128 / 2 + 255) / 256, 256>>>();
    // gate: [64,8192] = z @ w_ih.T + b_ih + b_hh   (fp16 HFMA2, KC=1, fused bias)
    gemm64h_f<NGATE, H128><<<NGATE / 64, 256>>>((const __half*)pz16, wih, bih, bhh, (float*)pgi);

    lstm_kernel<<<ncta, 1024, LSTM_SMEM>>>(whh, out, ncta);
}

// round 12
// speedup vs baseline: 1.0554x; 1.0554x over previous
#include <cuda_runtime.h>
#include <cuda_fp16.h>
#include <math.h>

// ---------------- problem dims ----------------
#define BB    64
#define NN    1024
#define H16   256
#define H64   1024
#define H128  2048
#define NGATE 8192

#define NCTA_MAX 148
#define WROWS 55                                 // gate rows resident in SMEM per CTA
// dynamic SMEM layout for lstm kernel
#define OFF_H16   (WROWS * 2048 * 2)             // 225280: fp16 h copy (4096 B)
#define OFF_G     (OFF_H16 + H128 * 2)           // gate preacts  (256 B)
#define OFF_C     (OFF_G + 64 * 4)               // cell state    (64 B)
#define LSTM_SMEM (OFF_C + 64)                   // 229696 B (<= 232448 max)

// ---------------- device scratch ----------------
__device__ __align__(16) float  g_x [BB * NN];
__device__ __align__(16) float  g_af[BB * H16];
__device__ __align__(16) float  g_ai[BB * H64];
__device__ __align__(16) __half g_z16[BB * H128];
__device__ __align__(16) float  g_gi[BB * NGATE];
__device__ __align__(16) float  g_part[1 << 21];     // split-K partials (8MB)
__device__ __align__(16) __half g_h16[2][H128];      // fp16 recurrent h (double-buffered)
__device__ unsigned g_slot[NCTA_MAX * 8];            // spread barrier slots (32B apart)

__global__ void reset_kernel() {
    for (int i = threadIdx.x; i < NCTA_MAX * 8; i += blockDim.x) g_slot[i] = 0u;
}

// ---------------- release/acquire helpers ----------------
__device__ __forceinline__ void st_release(unsigned* p, unsigned v) {
    asm volatile("st.release.gpu.global.u32 [%0], %1;" :: "l"(p), "r"(v) : "memory");
}
__device__ __forceinline__ unsigned ld_acquire(const unsigned* p) {
    unsigned v;
    asm volatile("ld.acquire.gpu.global.u32 %0, [%1];" : "=r"(v) : "l"(p) : "memory");
    return v;
}

// ---------------- GCN: one block per sample ----------------
__global__ __launch_bounds__(1024) void gcn_kernel(
    const float* __restrict__ inp,
    const float* __restrict__ gc1w, const float* __restrict__ gc1b,
    const float* __restrict__ gc2w, const float* __restrict__ gc2b)
{
    __shared__ float xs[NN];
    __shared__ float s2[NN];
    const int s = blockIdx.x;
    const int i = threadIdx.x;
    xs[i] = inp[s * NN + i];
    __syncthreads();
    const float xi = xs[i];

    float d0 = INFINITY, d1 = INFINITY, d2 = INFINITY, d3 = INFINITY;
    int i0 = 0, i1 = 0, i2 = 0, i3 = 0;
#pragma unroll 4
    for (int j = 0; j < NN; ++j) {
        float dj = fabsf(xi - xs[j]);
        if (j != i && dj < d3) {
            if (dj < d2) {
                d3 = d2; i3 = i2;
                if (dj < d1) {
                    d2 = d1; i2 = i1;
                    if (dj < d0) { d1 = d0; i1 = i0; d0 = dj; i0 = j; }
                    else         { d1 = dj; i1 = j; }
                } else { d2 = dj; i2 = j; }
            } else { d3 = dj; i3 = j; }
        }
    }

    float S = xs[i0] + xs[i1] + xs[i2] + xs[i3];
    float v = 0.f;
#pragma unroll
    for (int c = 0; c < 4; ++c) {
        float hc = fmaxf(gc1w[c] * S + gc1b[c], 0.f);
        v += hc * gc2w[c];
    }
    s2[i] = v;
    __syncthreads();
    g_x[s * NN + i] = s2[i0] + s2[i1] + s2[i2] + s2[i3] + gc2b[0];
}

// ---------------- small split-K GEMM (64xR', 128 thr) for fl/il ----------------
template <int R, int J, int KC>
__global__ __launch_bounds__(128) void gemm_sk(
    const float* __restrict__ A, const float* __restrict__ W, float* __restrict__ part)
{
    __shared__ float As[64][33];
    __shared__ float Ws[32][33];
    const int JC  = J / KC;
    const int kc  = blockIdx.y;
    const int br0 = blockIdx.x * 32;
    const int tid = threadIdx.x;
    const int tq  = tid & 15;
    const int rq  = tid >> 4;

    float acc[4][4];
#pragma unroll
    for (int a = 0; a < 4; ++a)
#pragma unroll
        for (int b = 0; b < 4; ++b) acc[a][b] = 0.f;

    const int j_end = (kc + 1) * JC;
    for (int j0 = kc * JC; j0 < j_end; j0 += 32) {
        for (int idx = tid; idx < 64 * 32; idx += 128) {
            int row = idx >> 5, col = idx & 31;
            As[row][col] = A[row * J + j0 + col];
        }
        for (int idx = tid; idx < 32 * 32; idx += 128) {
            int row = idx >> 5, col = idx & 31;
            Ws[row][col] = W[(size_t)(br0 + row) * J + j0 + col];
        }
        __syncthreads();
#pragma unroll
        for (int kk = 0; kk < 32; ++kk) {
            float av[4], wv[4];
#pragma unroll
            for (int a = 0; a < 4; ++a) av[a] = As[tq + 16 * a][kk];
#pragma unroll
            for (int b = 0; b < 4; ++b) wv[b] = Ws[rq + 8 * b][kk];
#pragma unroll
            for (int a = 0; a < 4; ++a)
#pragma unroll
                for (int b = 0; b < 4; ++b) acc[a][b] += av[a] * wv[b];
        }
        __syncthreads();
    }
#pragma unroll
    for (int a = 0; a < 4; ++a)
#pragma unroll
        for (int b = 0; b < 4; ++b)
            part[(size_t)kc * 64 * R + (tq + 16 * a) * R + br0 + rq + 8 * b] = acc[a][b];
}

// ---------------- big split-K fp32 GEMM (ol layer): 64x64 tile, double-buffered ----------------
template <int R, int J, int KC>
__global__ __launch_bounds__(256) void gemm64(
    const float* __restrict__ A, const float* __restrict__ W, float* __restrict__ part)
{
    __shared__ float As[2][64][33];
    __shared__ float Ws[2][64][33];
    const int JC  = J / KC;
    const int kc  = blockIdx.y;
    const int br0 = blockIdx.x * 64;
    const int tid = threadIdx.x;
    const int tq  = tid & 15;
    const int rq  = tid >> 4;

    float acc[4][4];
#pragma unroll
    for (int a = 0; a < 4; ++a)
#pragma unroll
        for (int b = 0; b < 4; ++b) acc[a][b] = 0.f;

    const int jbeg = kc * JC;
    const int nit  = JC / 32;

    auto load = [&](int s, int j0) {
#pragma unroll
        for (int idx = tid; idx < 64 * 32; idx += 256) {
            int row = idx >> 5, col = idx & 31;
            As[s][row][col] = A[row * J + j0 + col];
            Ws[s][row][col] = W[(size_t)(br0 + row) * J + j0 + col];
        }
    };

    load(0, jbeg);
    __syncthreads();
    for (int it = 0; it < nit; ++it) {
        int s = it & 1;
        if (it + 1 < nit) load(s ^ 1, jbeg + (it + 1) * 32);
#pragma unroll
        for (int kk = 0; kk < 32; ++kk) {
            float av[4], wv[4];
#pragma unroll
            for (int a = 0; a < 4; ++a) av[a] = As[s][tq + 16 * a][kk];
#pragma unroll
            for (int b = 0; b < 4; ++b) wv[b] = Ws[s][rq + 16 * b][kk];
#pragma unroll
            for (int a = 0; a < 4; ++a)
#pragma unroll
                for (int b = 0; b < 4; ++b) acc[a][b] += av[a] * wv[b];
        }
        __syncthreads();
    }
#pragma unroll
    for (int a = 0; a < 4; ++a)
#pragma unroll
        for (int b = 0; b < 4; ++b)
            part[(size_t)kc * 64 * R + (tq + 16 * a) * R + br0 + rq + 16 * b] = acc[a][b];
}

// ---------------- gate GEMM: fp16 HFMA2, split-K (R9-proven) ----------------
template <int R, int J, int KC>
__global__ __launch_bounds__(256) void gemm64h(
    const __half* __restrict__ A16, const float* __restrict__ W,
    float* __restrict__ part)
{
    __shared__ __half2 As[2][64][17];   // 16 half2 (=32 K) + 1 pad
    __shared__ __half2 Ws[2][64][17];
    const int JC  = J / KC;
    const int kc  = blockIdx.y;
    const int br0 = blockIdx.x * 64;
    const int tid = threadIdx.x;
    const int tq  = tid & 15;
    const int rq  = tid >> 4;

    float acc[4][4];
#pragma unroll
    for (int a = 0; a < 4; ++a)
#pragma unroll
        for (int b = 0; b < 4; ++b) acc[a][b] = 0.f;

    const int jbeg = kc * JC;
    const int nit  = JC / 32;
    const int row  = tid >> 2;          // 0..63
    const int c4   = tid & 3;           // 16B chunk within 32-half row slice

    auto load = [&](int s, int j0) {
        {
            uint4 v = *((const uint4*)(A16 + row * J + j0) + c4);
            const __half2* pv = (const __half2*)&v;
            __half2* d = &As[s][row][c4 * 4];
            d[0] = pv[0]; d[1] = pv[1]; d[2] = pv[2]; d[3] = pv[3];
        }
        {
            const float4* src = (const float4*)(W + (size_t)(br0 + row) * J + j0) + c4 * 2;
            float4 a = src[0], b = src[1];
            __half2* d = &Ws[s][row][c4 * 4];
            d[0] = __floats2half2_rn(a.x, a.y);
            d[1] = __floats2half2_rn(a.z, a.w);
            d[2] = __floats2half2_rn(b.x, b.y);
            d[3] = __floats2half2_rn(b.z, b.w);
        }
    };

    load(0, jbeg);
    __syncthreads();
    for (int it = 0; it < nit; ++it) {
        int s = it & 1;
        if (it + 1 < nit) load(s ^ 1, jbeg + (it + 1) * 32);
        __half2 h2[4][4];
        {
            __half2 av[4], wv[4];
#pragma unroll
            for (int a = 0; a < 4; ++a) av[a] = As[s][tq + 16 * a][0];
#pragma unroll
            for (int b = 0; b < 4; ++b) wv[b] = Ws[s][rq + 16 * b][0];
#pragma unroll
            for (int a = 0; a < 4; ++a)
#pragma unroll
                for (int b = 0; b < 4; ++b) h2[a][b] = __hmul2(av[a], wv[b]);
        }
#pragma unroll
        for (int kk = 1; kk < 16; ++kk) {
            __half2 av[4], wv[4];
#pragma unroll
            for (int a = 0; a < 4; ++a) av[a] = As[s][tq + 16 * a][kk];
#pragma unroll
            for (int b = 0; b < 4; ++b) wv[b] = Ws[s][rq + 16 * b][kk];
#pragma unroll
            for (int a = 0; a < 4; ++a)
#pragma unroll
                for (int b = 0; b < 4; ++b) h2[a][b] = __hfma2(av[a], wv[b], h2[a][b]);
        }
#pragma unroll
        for (int a = 0; a < 4; ++a)
#pragma unroll
            for (int b = 0; b < 4; ++b) {
                float2 f = __half22float2(h2[a][b]);
                acc[a][b] += f.x + f.y;
            }
        __syncthreads();
    }
#pragma unroll
    for (int a = 0; a < 4; ++a)
#pragma unroll
        for (int b = 0; b < 4; ++b)
            part[(size_t)kc * 64 * R + (tq + 16 * a) * R + br0 + rq + 16 * b] = acc[a][b];
}

// ---------------- reduce partials -> fp32 out ----------------
template <int R, int KC, bool RELU, bool HASB2>
__global__ __launch_bounds__(256) void reduce_k(
    const float* __restrict__ part,
    const float* __restrict__ b1, const float* __restrict__ b2,
    float* __restrict__ C)
{
    int i = blockIdx.x * 256 + threadIdx.x;
    if (i >= 64 * R) return;
    int r = i % R;
    float s = 0.f;
#pragma unroll
    for (int kc = 0; kc < KC; ++kc) s += part[(size_t)kc * 64 * R + i];
    s += b1[r];
    if (HASB2) s += b2[r];
    if (RELU) s = fmaxf(s, 0.f);
    C[i] = s;
}

// ---------------- reduce partials -> relu -> fp16 out (ol layer -> z16), half2 stores ----------------
template <int R, int KC>
__global__ __launch_bounds__(256) void reduce_k_h(
    const float* __restrict__ part, const float* __restrict__ b1,
    __half2* __restrict__ C2)
{
    int p = blockIdx.x * 256 + threadIdx.x;      // half2 index
    if (p >= 64 * R / 2) return;
    int i0 = 2 * p;
    int r0 = i0 % R;
    float s0 = 0.f, s1 = 0.f;
#pragma unroll
    for (int kc = 0; kc < KC; ++kc) {
        const float2 v = *(const float2*)&part[(size_t)kc * 64 * R + i0];
        s0 += v.x; s1 += v.y;
    }
    s0 = fmaxf(s0 + b1[r0], 0.f);
    s1 = fmaxf(s1 + b1[r0 + 1], 0.f);            // R even, i0 even -> same row
    C2[p] = __floats2half2_rn(s0, s1);
}

__device__ __forceinline__ float sigmoidf_(float x) { return 1.f / (1.f + expf(-x)); }

// ---------------- persistent LSTM: 55 SMEM rows, split-chain HFMA2, lean sync ----------------
__global__ __launch_bounds__(1024, 1) void lstm_kernel(
    const float* __restrict__ w_hh, float* __restrict__ out, int ncta)
{
    extern __shared__ unsigned char sm[];
    __half* w_sm = (__half*)sm;                     // [WROWS][2048] fp16, row = lr
    __half* h16  = (__half*)(sm + OFF_H16);         // [2048]
    float*  gsm  = (float*)(sm + OFF_G);            // [64]
    float*  csm  = (float*)(sm + OFF_C);            // [16]

    const int tid  = threadIdx.x;
    const int bid  = blockIdx.x;
    const int warp = tid >> 5, lane = tid & 31;

    const int base = H128 / ncta;
    const int rem  = H128 - base * ncta;
    const int nu   = (bid < rem) ? base + 1 : base;
    const int u0   = bid * base + min(bid, rem);
    const int nrows = 4 * nu;
    const int wrows = (nrows < WROWS) ? nrows : WROWS;   // rows resident in SMEM

    // prologue: convert resident rows fp32 -> fp16, SMEM row index = lr
    {
        const int tot2 = wrows * 1024;              // half2 count
        __half2* dst = (__half2*)w_sm;
        for (int idx = tid; idx < tot2; idx += 1024) {
            int lr = idx >> 10, c2 = idx & 1023;
            int g = lr / nu, ui = lr - g * nu;
            const float2* src = (const float2*)(w_hh + (size_t)(g * H128 + u0 + ui) * H128);
            float2 v = src[c2];
            dst[idx] = __floats2half2_rn(v.x, v.y);
        }
    }

    // per-warp row assignment: lr = warp + 32*k (cnt uniform per warp)
    int cnt = 0;
    int rowg[2], gsl[2];
    bool insm[2];
    const uint4*  wr16[2];
    const float4* wr32[2];
#pragma unroll
    for (int k = 0; k < 2; ++k) {
        int lr = warp + 32 * k;
        if (lr < nrows) {
            int g = lr / nu, ui = lr - g * nu;
            rowg[cnt] = g * H128 + u0 + ui;
            gsl [cnt] = lr;
            insm[cnt] = (lr < wrows);
            wr16[cnt] = (const uint4*)(w_sm + (size_t)lr * H128);
            wr32[cnt] = (const float4*)(w_hh + (size_t)rowg[cnt] * H128);
            ++cnt;
        }
    }

    if (tid < nu) { csm[tid] = 0.f; g_h16[0][u0 + tid] = __float2half(0.f); }
    __syncthreads();
    if (tid == 0) st_release(&g_slot[bid * 8], 1u);
    if (tid < ncta) { while (ld_acquire(&g_slot[tid * 8]) < 1u) {} }
    __syncthreads();

    for (int t = 0; t < BB; ++t) {
        // broadcast h into SMEM (already fp16 in global)
        if (tid < H128 / 8) {
            uint4 v = __ldcg((const uint4*)g_h16[t & 1] + tid);
            ((uint4*)h16)[tid] = v;
        }
        // prefetch gate-input terms (L2-resident)
        float gi[2] = {0.f, 0.f};
        if (lane == 0) {
#pragma unroll
            for (int k = 0; k < 2; ++k)
                if (k < cnt) gi[k] = g_gi[t * NGATE + rowg[k]];
        }
        __syncthreads();

        float acc[2] = {0.f, 0.f};
        const uint4* h16u = (const uint4*)h16;
#pragma unroll
        for (int ii = 0; ii < 4; ++ii) {
            const int o = lane + 64 * ii;
            uint4 ha = h16u[o], hb = h16u[o + 32];
            const __half2* hpa = (const __half2*)&ha;
            const __half2* hpb = (const __half2*)&hb;
#pragma unroll
            for (int k = 0; k < 2; ++k) {
                if (k >= cnt) break;                 // warp-uniform branch
                __half2 sa, sb;                      // two independent chains (ILP)
                if (insm[k]) {
                    uint4 wa = wr16[k][o], wb = wr16[k][o + 32];
                    const __half2* wpa = (const __half2*)&wa;
                    const __half2* wpb = (const __half2*)&wb;
                    sa = __hmul2(wpa[0], hpa[0]);
                    sb = __hmul2(wpb[0], hpb[0]);
                    sa = __hfma2(wpa[1], hpa[1], sa);
                    sb = __hfma2(wpb[1], hpb[1], sb);
                    sa = __hfma2(wpa[2], hpa[2], sa);
                    sb = __hfma2(wpb[2], hpb[2], sb);
                    sa = __hfma2(wpa[3], hpa[3], sa);
                    sb = __hfma2(wpb[3], hpb[3], sb);
                } else {
                    float4 a0 = __ldg(wr32[k] + 2 * o);
                    float4 a1 = __ldg(wr32[k] + 2 * o + 1);
                    float4 b0 = __ldg(wr32[k] + 2 * (o + 32));
                    float4 b1 = __ldg(wr32[k] + 2 * (o + 32) + 1);
                    sa = __hmul2(__floats2half2_rn(a0.x, a0.y), hpa[0]);
                    sb = __hmul2(__floats2half2_rn(b0.x, b0.y), hpb[0]);
                    sa = __hfma2(__floats2half2_rn(a0.z, a0.w), hpa[1], sa);
                    sb = __hfma2(__floats2half2_rn(b0.z, b0.w), hpb[1], sb);
                    sa = __hfma2(__floats2half2_rn(a1.x, a1.y), hpa[2], sa);
                    sb = __hfma2(__floats2half2_rn(b1.x, b1.y), hpb[2], sb);
                    sa = __hfma2(__floats2half2_rn(a1.z, a1.w), hpa[3], sa);
                    sb = __hfma2(__floats2half2_rn(b1.z, b1.w), hpb[3], sb);
                }
                float2 fa = __half22float2(sa);
                float2 fb = __half22float2(sb);
                acc[k] += (fa.x + fa.y) + (fb.x + fb.y);
            }
        }
#pragma unroll
        for (int k = 0; k < 2; ++k)
#pragma unroll
            for (int o = 16; o > 0; o >>= 1) acc[k] += __shfl_xor_sync(0xffffffffu, acc[k], o);
        if (lane == 0) {
#pragma unroll
            for (int k = 0; k < 2; ++k)
                if (k < cnt) gsm[gsl[k]] = acc[k] + gi[k];
        }
        __syncthreads();

        // warp 0: activation epilogue + h publish + release (no extra CTA barrier)
        if (warp == 0) {
            if (tid < nu) {
                float ig = gsm[tid], fg = gsm[nu + tid], gg = gsm[2 * nu + tid], og = gsm[3 * nu + tid];
                float c = sigmoidf_(fg) * csm[tid] + sigmoidf_(ig) * tanhf(gg);
                float h = sigmoidf_(og) * tanhf(c);
                csm[tid] = c;
                g_h16[(t + 1) & 1][u0 + tid] = __float2half(h);
                out[t * H128 + u0 + tid] = h;
            }
            __syncwarp();
            if (tid == 0) st_release(&g_slot[bid * 8], (unsigned)(t + 2));
        }
        if (tid < ncta) { unsigned tgt = (unsigned)(t + 2); while (ld_acquire(&g_slot[tid * 8]) < tgt) {} }
        __syncthreads();
    }
}

// ---------------- launch ----------------
extern "C" void kernel_launch(void* const* d_in, const int* in_sizes, int n_in,
                              void* d_out, int out_size)
{
    const float* inp  = (const float*)d_in[0];
    const float* gc1w = (const float*)d_in[3];
    const float* gc1b = (const float*)d_in[4];
    const float* gc2w = (const float*)d_in[5];
    const float* gc2b = (const float*)d_in[6];
    const float* flw  = (const float*)d_in[7];
    const float* flb  = (const float*)d_in[8];
    const float* ilw  = (const float*)d_in[9];
    const float* ilb  = (const float*)d_in[10];
    const float* olw  = (const float*)d_in[11];
    const float* olb  = (const float*)d_in[12];
    const float* wih  = (const float*)d_in[13];
    const float* whh  = (const float*)d_in[14];
    const float* bih  = (const float*)d_in[15];
    const float* bhh  = (const float*)d_in[16];
    float* out = (float*)d_out;

    void *px, *paf, *pai, *pz16, *pgi, *ppart;
    cudaGetSymbolAddress(&px,    g_x);
    cudaGetSymbolAddress(&paf,   g_af);
    cudaGetSymbolAddress(&pai,   g_ai);
    cudaGetSymbolAddress(&pz16,  g_z16);
    cudaGetSymbolAddress(&pgi,   g_gi);
    cudaGetSymbolAddress(&ppart, g_part);
    float* part = (float*)ppart;

    int sms = 0;
    cudaDeviceGetAttribute(&sms, cudaDevAttrMultiProcessorCount, 0);
    int ncta = sms;
    if (ncta > NCTA_MAX) ncta = NCTA_MAX;
    if (ncta < 128) ncta = 128;

    cudaFuncSetAttribute(lstm_kernel, cudaFuncAttributeMaxDynamicSharedMemorySize, LSTM_SMEM);

    reset_kernel<<<1, 256>>>();
    gcn_kernel<<<BB, NN>>>(inp, gc1w, gc1b, gc2w, gc2b);

    // fl: [64,256] = x @ fl_w.T ; relu
    gemm_sk<H16, NN, 16><<<dim3(H16 / 32, 16), 128>>>((const float*)px, flw, part);
    reduce_k<H16, 16, true, false><<<(64 * H16 + 255) / 256, 256>>>(part, flb, nullptr, (float*)paf);
    // il: [64,1024] = af @ il_w.T ; relu
    gemm_sk<H64, H16, 4><<<dim3(H64 / 32, 4), 128>>>((const float*)paf, ilw, part);
    reduce_k<H64, 4, true, false><<<(64 * H64 + 255) / 256, 256>>>(part, ilb, nullptr, (float*)pai);
    // ol: [64,2048] = ai @ ol_w.T ; relu -> z16 (fp16 direct, half2 stores)
    gemm64<H128, H64, 4><<<dim3(H128 / 64, 4), 256>>>((const float*)pai, olw, part);
    reduce_k_h<H128, 4><<<(64 * H128 / 2 + 255) / 256, 256>>>(part, olb, (__half2*)pz16);
    // gate: [64,8192] = z @ w_ih.T + b_ih + b_hh   (fp16 HFMA2, split-K KC=4)
    gemm64h<NGATE, H128, 4><<<dim3(NGATE / 64, 4), 256>>>((const __half*)pz16, wih, part);
    reduce_k<NGATE, 4, false, true><<<(64 * NGATE + 255) / 256, 256>>>(part, bih, bhh, (float*)pgi);

    lstm_kernel<<<ncta, 1024, LSTM_SMEM>>>(whh, out, ncta);
}

// round 14
// speedup vs baseline: 1.0822x; 1.0254x over previous
#include <cuda_runtime.h>
#include <cuda_fp16.h>
#include <cstdint>
#include <math.h>

// ---------------- problem dims ----------------
#define BB    64
#define NN    1024
#define H16   256
#define H64   1024
#define H128  2048
#define NGATE 8192

#define NCTA_MAX 148
#define WROWS 55                                 // gate rows resident in SMEM per CTA
// dynamic SMEM layout for lstm kernel
#define OFF_H16   (WROWS * 2048 * 2)             // 225280: fp16 h copy (4096 B)
#define OFF_G     (OFF_H16 + H128 * 2)           // gate preacts  (256 B)
#define OFF_C     (OFF_G + 64 * 4)               // cell state    (64 B)
#define LSTM_SMEM (OFF_C + 64)                   // 229696 B (<= 232448 max)

// ---------------- device scratch ----------------
__device__ __align__(16) float  g_x [BB * NN];
__device__ __align__(16) float  g_af[BB * H16];
__device__ __align__(16) float  g_ai[BB * H64];
__device__ __align__(16) __half g_z16[BB * H128];
__device__ __align__(16) float  g_gi[BB * NGATE];
__device__ __align__(16) float  g_part[1 << 21];     // split-K partials (8MB)
__device__ __align__(16) __half g_h16[2][H128];      // fp16 recurrent h (double-buffered)
__device__ unsigned g_slot[NCTA_MAX * 8];            // spread barrier slots (32B apart)

// ---------------- release/acquire helpers ----------------
__device__ __forceinline__ void st_release(unsigned* p, unsigned v) {
    asm volatile("st.release.gpu.global.u32 [%0], %1;" :: "l"(p), "r"(v) : "memory");
}
__device__ __forceinline__ unsigned ld_acquire(const unsigned* p) {
    unsigned v;
    asm volatile("ld.acquire.gpu.global.u32 %0, [%1];" : "=r"(v) : "l"(p) : "memory");
    return v;
}

// ---------------- GCN: one block per sample (block 0 also resets barrier slots) ----------------
__global__ __launch_bounds__(1024) void gcn_kernel(
    const float* __restrict__ inp,
    const float* __restrict__ gc1w, const float* __restrict__ gc1b,
    const float* __restrict__ gc2w, const float* __restrict__ gc2b)
{
    __shared__ float xs[NN];
    __shared__ float s2[NN];
    const int s = blockIdx.x;
    const int i = threadIdx.x;
    if (s == 0 && i < NCTA_MAX * 8) g_slot[i] = 0u;   // fold reset here (lstm runs later)
    xs[i] = inp[s * NN + i];
    __syncthreads();
    const float xi = xs[i];

    float d0 = INFINITY, d1 = INFINITY, d2 = INFINITY, d3 = INFINITY;
    int i0 = 0, i1 = 0, i2 = 0, i3 = 0;
#pragma unroll 4
    for (int j = 0; j < NN; ++j) {
        float dj = fabsf(xi - xs[j]);
        if (j != i && dj < d3) {
            if (dj < d2) {
                d3 = d2; i3 = i2;
                if (dj < d1) {
                    d2 = d1; i2 = i1;
                    if (dj < d0) { d1 = d0; i1 = i0; d0 = dj; i0 = j; }
                    else         { d1 = dj; i1 = j; }
                } else { d2 = dj; i2 = j; }
            } else { d3 = dj; i3 = j; }
        }
    }

    float S = xs[i0] + xs[i1] + xs[i2] + xs[i3];
    float v = 0.f;
#pragma unroll
    for (int c = 0; c < 4; ++c) {
        float hc = fmaxf(gc1w[c] * S + gc1b[c], 0.f);
        v += hc * gc2w[c];
    }
    s2[i] = v;
    __syncthreads();
    g_x[s * NN + i] = s2[i0] + s2[i1] + s2[i2] + s2[i3] + gc2b[0];
}

// ---------------- small split-K GEMM (64xR', 128 thr) for fl/il ----------------
template <int R, int J, int KC>
__global__ __launch_bounds__(128) void gemm_sk(
    const float* __restrict__ A, const float* __restrict__ W, float* __restrict__ part)
{
    __shared__ float As[64][33];
    __shared__ float Ws[32][33];
    const int JC  = J / KC;
    const int kc  = blockIdx.y;
    const int br0 = blockIdx.x * 32;
    const int tid = threadIdx.x;
    const int tq  = tid & 15;
    const int rq  = tid >> 4;

    float acc[4][4];
#pragma unroll
    for (int a = 0; a < 4; ++a)
#pragma unroll
        for (int b = 0; b < 4; ++b) acc[a][b] = 0.f;

    const int j_end = (kc + 1) * JC;
    for (int j0 = kc * JC; j0 < j_end; j0 += 32) {
        for (int idx = tid; idx < 64 * 32; idx += 128) {
            int row = idx >> 5, col = idx & 31;
            As[row][col] = A[row * J + j0 + col];
        }
        for (int idx = tid; idx < 32 * 32; idx += 128) {
            int row = idx >> 5, col = idx & 31;
            Ws[row][col] = W[(size_t)(br0 + row) * J + j0 + col];
        }
        __syncthreads();
#pragma unroll
        for (int kk = 0; kk < 32; ++kk) {
            float av[4], wv[4];
#pragma unroll
            for (int a = 0; a < 4; ++a) av[a] = As[tq + 16 * a][kk];
#pragma unroll
            for (int b = 0; b < 4; ++b) wv[b] = Ws[rq + 8 * b][kk];
#pragma unroll
            for (int a = 0; a < 4; ++a)
#pragma unroll
                for (int b = 0; b < 4; ++b) acc[a][b] += av[a] * wv[b];
        }
        __syncthreads();
    }
#pragma unroll
    for (int a = 0; a < 4; ++a)
#pragma unroll
        for (int b = 0; b < 4; ++b)
            part[(size_t)kc * 64 * R + (tq + 16 * a) * R + br0 + rq + 8 * b] = acc[a][b];
}

// ---------------- big split-K fp32 GEMM (ol layer): 64x64 tile, double-buffered ----------------
template <int R, int J, int KC>
__global__ __launch_bounds__(256) void gemm64(
    const float* __restrict__ A, const float* __restrict__ W, float* __restrict__ part)
{
    __shared__ float As[2][64][33];
    __shared__ float Ws[2][64][33];
    const int JC  = J / KC;
    const int kc  = blockIdx.y;
    const int br0 = blockIdx.x * 64;
    const int tid = threadIdx.x;
    const int tq  = tid & 15;
    const int rq  = tid >> 4;

    float acc[4][4];
#pragma unroll
    for (int a = 0; a < 4; ++a)
#pragma unroll
        for (int b = 0; b < 4; ++b) acc[a][b] = 0.f;

    const int jbeg = kc * JC;
    const int nit  = JC / 32;

    auto load = [&](int s, int j0) {
#pragma unroll
        for (int idx = tid; idx < 64 * 32; idx += 256) {
            int row = idx >> 5, col = idx & 31;
            As[s][row][col] = A[row * J + j0 + col];
            Ws[s][row][col] = W[(size_t)(br0 + row) * J + j0 + col];
        }
    };

    load(0, jbeg);
    __syncthreads();
    for (int it = 0; it < nit; ++it) {
        int s = it & 1;
        if (it + 1 < nit) load(s ^ 1, jbeg + (it + 1) * 32);
#pragma unroll
        for (int kk = 0; kk < 32; ++kk) {
            float av[4], wv[4];
#pragma unroll
            for (int a = 0; a < 4; ++a) av[a] = As[s][tq + 16 * a][kk];
#pragma unroll
            for (int b = 0; b < 4; ++b) wv[b] = Ws[s][rq + 16 * b][kk];
#pragma unroll
            for (int a = 0; a < 4; ++a)
#pragma unroll
                for (int b = 0; b < 4; ++b) acc[a][b] += av[a] * wv[b];
        }
        __syncthreads();
    }
#pragma unroll
    for (int a = 0; a < 4; ++a)
#pragma unroll
        for (int b = 0; b < 4; ++b)
            part[(size_t)kc * 64 * R + (tq + 16 * a) * R + br0 + rq + 16 * b] = acc[a][b];
}

// ---------------- gate GEMM: tensor-core mma.sync m16n8k16 ----------------
// part[kc][t][r] = sum_{j in chunk} z16[t][j] * half(w_ih[r][j]); fp32 mma accumulation.
template <int R, int J, int KC>
__global__ __launch_bounds__(128) void gemm_mma(
    const __half* __restrict__ A16, const float* __restrict__ W,
    float* __restrict__ part)
{
    constexpr int LDA = 72;                     // halfs per SMEM row (64 + 8 pad)
    __shared__ __half Asm[2][64 * LDA];
    __shared__ __half Bsm[2][64 * LDA];
    const int JC  = J / KC;                     // 512
    const int kc  = blockIdx.y;
    const int br0 = blockIdx.x * 64;
    const int tid = threadIdx.x;
    const int warp = tid >> 5, lane = tid & 31;
    const int nit = JC / 64;                    // 8 chunks of K=64

    float acc[8][4];
#pragma unroll
    for (int nf = 0; nf < 8; ++nf)
#pragma unroll
        for (int q = 0; q < 4; ++q) acc[nf][q] = 0.f;

    const int lrow = tid >> 1;                  // 0..63
    const int lcol = (tid & 1) * 32;            // half-row split

    auto loadA = [&](int s, int j0) {
        const uint4* src = (const uint4*)(A16 + lrow * J + j0 + lcol);
        uint4* dst = (uint4*)(Asm[s] + lrow * LDA + lcol);
#pragma unroll
        for (int q = 0; q < 4; ++q) dst[q] = src[q];
    };
    auto loadB = [&](int s, int j0) {
        const float4* src = (const float4*)(W + (size_t)(br0 + lrow) * J + j0 + lcol);
        __half2* dst = (__half2*)(Bsm[s] + lrow * LDA + lcol);
#pragma unroll
        for (int q = 0; q < 8; ++q) {
            float4 v = src[q];
            dst[2 * q]     = __floats2half2_rn(v.x, v.y);
            dst[2 * q + 1] = __floats2half2_rn(v.z, v.w);
        }
    };

    const int jbeg = kc * JC;
    loadA(0, jbeg); loadB(0, jbeg);
    __syncthreads();

    for (int it = 0; it < nit; ++it) {
        const int s = it & 1;
        if (it + 1 < nit) { loadA(s ^ 1, jbeg + (it + 1) * 64); loadB(s ^ 1, jbeg + (it + 1) * 64); }

        const __half* As = Asm[s];
        const __half* Bs = Bsm[s];
#pragma unroll
        for (int k16 = 0; k16 < 4; ++k16) {
            // A fragment: rows warp*16 + (lane&15), k-half (lane>>4)*8
            uint32_t a0, a1, a2, a3;
            {
                const __half* ap = As + (warp * 16 + (lane & 15)) * LDA + k16 * 16 + (lane >> 4) * 8;
                uint32_t addr = (uint32_t)__cvta_generic_to_shared(ap);
                asm volatile("ldmatrix.sync.aligned.m8n8.x4.shared.b16 {%0,%1,%2,%3}, [%4];"
                             : "=r"(a0), "=r"(a1), "=r"(a2), "=r"(a3) : "r"(addr));
            }
            // B fragments: two n8-groups per ldmatrix.x4 (rows = n, cols = k)
#pragma unroll
            for (int ng = 0; ng < 4; ++ng) {
                uint32_t r0, r1, r2, r3;
                const __half* bp = Bs + (ng * 16 + (lane & 15)) * LDA + k16 * 16 + (lane >> 4) * 8;
                uint32_t addr = (uint32_t)__cvta_generic_to_shared(bp);
                asm volatile("ldmatrix.sync.aligned.m8n8.x4.shared.b16 {%0,%1,%2,%3}, [%4];"
                             : "=r"(r0), "=r"(r1), "=r"(r2), "=r"(r3) : "r"(addr));
                // n-group 2*ng   : {r0, r2};  n-group 2*ng+1 : {r1, r3}
                float* c0 = acc[2 * ng];
                asm volatile("mma.sync.aligned.m16n8k16.row.col.f32.f16.f16.f32 "
                             "{%0,%1,%2,%3}, {%4,%5,%6,%7}, {%8,%9}, {%0,%1,%2,%3};"
                             : "+f"(c0[0]), "+f"(c0[1]), "+f"(c0[2]), "+f"(c0[3])
                             : "r"(a0), "r"(a1), "r"(a2), "r"(a3), "r"(r0), "r"(r2));
                float* c1 = acc[2 * ng + 1];
                asm volatile("mma.sync.aligned.m16n8k16.row.col.f32.f16.f16.f32 "
                             "{%0,%1,%2,%3}, {%4,%5,%6,%7}, {%8,%9}, {%0,%1,%2,%3};"
                             : "+f"(c1[0]), "+f"(c1[1]), "+f"(c1[2]), "+f"(c1[3])
                             : "r"(a0), "r"(a1), "r"(a2), "r"(a3), "r"(r1), "r"(r3));
            }
        }
        __syncthreads();
    }

    // epilogue: D layout — c0,c1: (m = warp*16 + lane/4, r = nf*8 + (lane%4)*2 +0/1); c2,c3: m+8
    const int m0 = warp * 16 + (lane >> 2);
    const int rb = (lane & 3) * 2;
    float* base = part + (size_t)kc * 64 * R;
#pragma unroll
    for (int nf = 0; nf < 8; ++nf) {
        int r = br0 + nf * 8 + rb;
        *(float2*)&base[(size_t)m0 * R + r]       = make_float2(acc[nf][0], acc[nf][1]);
        *(float2*)&base[(size_t)(m0 + 8) * R + r] = make_float2(acc[nf][2], acc[nf][3]);
    }
}

// ---------------- reduce partials -> fp32 out ----------------
template <int R, int KC, bool RELU, bool HASB2>
__global__ __launch_bounds__(256) void reduce_k(
    const float* __restrict__ part,
    const float* __restrict__ b1, const float* __restrict__ b2,
    float* __restrict__ C)
{
    int i = blockIdx.x * 256 + threadIdx.x;
    if (i >= 64 * R) return;
    int r = i % R;
    float s = 0.f;
#pragma unroll
    for (int kc = 0; kc < KC; ++kc) s += part[(size_t)kc * 64 * R + i];
    s += b1[r];
    if (HASB2) s += b2[r];
    if (RELU) s = fmaxf(s, 0.f);
    C[i] = s;
}

// ---------------- reduce partials -> relu -> fp16 out (ol layer -> z16), half2 stores ----------------
template <int R, int KC>
__global__ __launch_bounds__(256) void reduce_k_h(
    const float* __restrict__ part, const float* __restrict__ b1,
    __half2* __restrict__ C2)
{
    int p = blockIdx.x * 256 + threadIdx.x;      // half2 index
    if (p >= 64 * R / 2) return;
    int i0 = 2 * p;
    int r0 = i0 % R;
    float s0 = 0.f, s1 = 0.f;
#pragma unroll
    for (int kc = 0; kc < KC; ++kc) {
        const float2 v = *(const float2*)&part[(size_t)kc * 64 * R + i0];
        s0 += v.x; s1 += v.y;
    }
    s0 = fmaxf(s0 + b1[r0], 0.f);
    s1 = fmaxf(s1 + b1[r0 + 1], 0.f);
    C2[p] = __floats2half2_rn(s0, s1);
}

__device__ __forceinline__ float sigmoidf_(float x) { return 1.f / (1.f + expf(-x)); }

// ---------------- persistent LSTM: 55 SMEM rows, split-chain HFMA2, lean sync ----------------
__global__ __launch_bounds__(1024, 1) void lstm_kernel(
    const float* __restrict__ w_hh, float* __restrict__ out, int ncta)
{
    extern __shared__ unsigned char sm[];
    __half* w_sm = (__half*)sm;                     // [WROWS][2048] fp16, row = lr
    __half* h16  = (__half*)(sm + OFF_H16);         // [2048]
    float*  gsm  = (float*)(sm + OFF_G);            // [64]
    float*  csm  = (float*)(sm + OFF_C);            // [16]

    const int tid  = threadIdx.x;
    const int bid  = blockIdx.x;
    const int warp = tid >> 5, lane = tid & 31;

    const int base = H128 / ncta;
    const int rem  = H128 - base * ncta;
    const int nu   = (bid < rem) ? base + 1 : base;
    const int u0   = bid * base + min(bid, rem);
    const int nrows = 4 * nu;
    const int wrows = (nrows < WROWS) ? nrows : WROWS;   // rows resident in SMEM

    // prologue: convert resident rows fp32 -> fp16, SMEM row index = lr
    {
        const int tot2 = wrows * 1024;              // half2 count
        __half2* dst = (__half2*)w_sm;
        for (int idx = tid; idx < tot2; idx += 1024) {
            int lr = idx >> 10, c2 = idx & 1023;
            int g = lr / nu, ui = lr - g * nu;
            const float2* src = (const float2*)(w_hh + (size_t)(g * H128 + u0 + ui) * H128);
            float2 v = src[c2];
            dst[idx] = __floats2half2_rn(v.x, v.y);
        }
    }

    // per-warp row assignment: lr = warp + 32*k (cnt uniform per warp)
    int cnt = 0;
    int rowg[2], gsl[2];
    bool insm[2];
    const uint4*  wr16[2];
    const float4* wr32[2];
#pragma unroll
    for (int k = 0; k < 2; ++k) {
        int lr = warp + 32 * k;
        if (lr < nrows) {
            int g = lr / nu, ui = lr - g * nu;
            rowg[cnt] = g * H128 + u0 + ui;
            gsl [cnt] = lr;
            insm[cnt] = (lr < wrows);
            wr16[cnt] = (const uint4*)(w_sm + (size_t)lr * H128);
            wr32[cnt] = (const float4*)(w_hh + (size_t)rowg[cnt] * H128);
            ++cnt;
        }
    }

    if (tid < nu) { csm[tid] = 0.f; g_h16[0][u0 + tid] = __float2half(0.f); }
    __syncthreads();
    if (tid == 0) st_release(&g_slot[bid * 8], 1u);
    if (tid < ncta) { while (ld_acquire(&g_slot[tid * 8]) < 1u) {} }
    __syncthreads();

    for (int t = 0; t < BB; ++t) {
        // broadcast h into SMEM (already fp16 in global)
        if (tid < H128 / 8) {
            uint4 v = __ldcg((const uint4*)g_h16[t & 1] + tid);
            ((uint4*)h16)[tid] = v;
        }
        // prefetch gate-input terms (L2-resident)
        float gi[2] = {0.f, 0.f};
        if (lane == 0) {
#pragma unroll
            for (int k = 0; k < 2; ++k)
                if (k < cnt) gi[k] = g_gi[t * NGATE + rowg[k]];
        }
        __syncthreads();

        float acc[2] = {0.f, 0.f};
        const uint4* h16u = (const uint4*)h16;
#pragma unroll
        for (int ii = 0; ii < 4; ++ii) {
            const int o = lane + 64 * ii;
            uint4 ha = h16u[o], hb = h16u[o + 32];
            const __half2* hpa = (const __half2*)&ha;
            const __half2* hpb = (const __half2*)&hb;
#pragma unroll
            for (int k = 0; k < 2; ++k) {
                if (k >= cnt) break;                 // warp-uniform branch
                __half2 sa, sb;                      // two independent chains (ILP)
                if (insm[k]) {
                    uint4 wa = wr16[k][o], wb = wr16[k][o + 32];
                    const __half2* wpa = (const __half2*)&wa;
                    const __half2* wpb = (const __half2*)&wb;
                    sa = __hmul2(wpa[0], hpa[0]);
                    sb = __hmul2(wpb[0], hpb[0]);
                    sa = __hfma2(wpa[1], hpa[1], sa);
                    sb = __hfma2(wpb[1], hpb[1], sb);
                    sa = __hfma2(wpa[2], hpa[2], sa);
                    sb = __hfma2(wpb[2], hpb[2], sb);
                    sa = __hfma2(wpa[3], hpa[3], sa);
                    sb = __hfma2(wpb[3], hpb[3], sb);
                } else {
                    float4 a0 = __ldg(wr32[k] + 2 * o);
                    float4 a1 = __ldg(wr32[k] + 2 * o + 1);
                    float4 b0 = __ldg(wr32[k] + 2 * (o + 32));
                    float4 b1 = __ldg(wr32[k] + 2 * (o + 32) + 1);
                    sa = __hmul2(__floats2half2_rn(a0.x, a0.y), hpa[0]);
                    sb = __hmul2(__floats2half2_rn(b0.x, b0.y), hpb[0]);
                    sa = __hfma2(__floats2half2_rn(a0.z, a0.w), hpa[1], sa);
                    sb = __hfma2(__floats2half2_rn(b0.z, b0.w), hpb[1], sb);
                    sa = __hfma2(__floats2half2_rn(a1.x, a1.y), hpa[2], sa);
                    sb = __hfma2(__floats2half2_rn(b1.x, b1.y), hpb[2], sb);
                    sa = __hfma2(__floats2half2_rn(a1.z, a1.w), hpa[3], sa);
                    sb = __hfma2(__floats2half2_rn(b1.z, b1.w), hpb[3], sb);
                }
                float2 fa = __half22float2(sa);
                float2 fb = __half22float2(sb);
                acc[k] += (fa.x + fa.y) + (fb.x + fb.y);
            }
        }
#pragma unroll
        for (int k = 0; k < 2; ++k)
#pragma unroll
            for (int o = 16; o > 0; o >>= 1) acc[k] += __shfl_xor_sync(0xffffffffu, acc[k], o);
        if (lane == 0) {
#pragma unroll
            for (int k = 0; k < 2; ++k)
                if (k < cnt) gsm[gsl[k]] = acc[k] + gi[k];
        }
        __syncthreads();

        // warp 0: activation epilogue + h publish + release (no extra CTA barrier)
        if (warp == 0) {
            if (tid < nu) {
                float ig = gsm[tid], fg = gsm[nu + tid], gg = gsm[2 * nu + tid], og = gsm[3 * nu + tid];
                float c = sigmoidf_(fg) * csm[tid] + sigmoidf_(ig) * tanhf(gg);
                float h = sigmoidf_(og) * tanhf(c);
                csm[tid] = c;
                g_h16[(t + 1) & 1][u0 + tid] = __float2half(h);
                out[t * H128 + u0 + tid] = h;
            }
            __syncwarp();
            if (tid == 0) st_release(&g_slot[bid * 8], (unsigned)(t + 2));
        }
        if (tid < ncta) { unsigned tgt = (unsigned)(t + 2); while (ld_acquire(&g_slot[tid * 8]) < tgt) {} }
        __syncthreads();
    }
}

// ---------------- launch ----------------
extern "C" void kernel_launch(void* const* d_in, const int* in_sizes, int n_in,
                              void* d_out, int out_size)
{
    const float* inp  = (const float*)d_in[0];
    const float* gc1w = (const float*)d_in[3];
    const float* gc1b = (const float*)d_in[4];
    const float* gc2w = (const float*)d_in[5];
    const float* gc2b = (const float*)d_in[6];
    const float* flw  = (const float*)d_in[7];
    const float* flb  = (const float*)d_in[8];
    const float* ilw  = (const float*)d_in[9];
    const float* ilb  = (const float*)d_in[10];
    const float* olw  = (const float*)d_in[11];
    const float* olb  = (const float*)d_in[12];
    const float* wih  = (const float*)d_in[13];
    const float* whh  = (const float*)d_in[14];
    const float* bih  = (const float*)d_in[15];
    const float* bhh  = (const float*)d_in[16];
    float* out = (float*)d_out;

    void *px, *paf, *pai, *pz16, *pgi, *ppart;
    cudaGetSymbolAddress(&px,    g_x);
    cudaGetSymbolAddress(&paf,   g_af);
    cudaGetSymbolAddress(&pai,   g_ai);
    cudaGetSymbolAddress(&pz16,  g_z16);
    cudaGetSymbolAddress(&pgi,   g_gi);
    cudaGetSymbolAddress(&ppart, g_part);
    float* part = (float*)ppart;

    int sms = 0;
    cudaDeviceGetAttribute(&sms, cudaDevAttrMultiProcessorCount, 0);
    int ncta = sms;
    if (ncta > NCTA_MAX) ncta = NCTA_MAX;
    if (ncta < 128) ncta = 128;

    cudaFuncSetAttribute(lstm_kernel, cudaFuncAttributeMaxDynamicSharedMemorySize, LSTM_SMEM);

    gcn_kernel<<<BB, NN>>>(inp, gc1w, gc1b, gc2w, gc2b);   // also resets g_slot

    // fl: [64,256] = x @ fl_w.T ; relu
    gemm_sk<H16, NN, 16><<<dim3(H16 / 32, 16), 128>>>((const float*)px, flw, part);
    reduce_k<H16, 16, true, false><<<(64 * H16 + 255) / 256, 256>>>(part, flb, nullptr, (float*)paf);
    // il: [64,1024] = af @ il_w.T ; relu
    gemm_sk<H64, H16, 4><<<dim3(H64 / 32, 4), 128>>>((const float*)paf, ilw, part);
    reduce_k<H64, 4, true, false><<<(64 * H64 + 255) / 256, 256>>>(part, ilb, nullptr, (float*)pai);
    // ol: [64,2048] = ai @ ol_w.T ; relu -> z16 (fp16 direct, half2 stores)
    gemm64<H128, H64, 4><<<dim3(H128 / 64, 4), 256>>>((const float*)pai, olw, part);
    reduce_k_h<H128, 4><<<(64 * H128 / 2 + 255) / 256, 256>>>(part, olb, (__half2*)pz16);
    // gate: [64,8192] = z @ w_ih.T + b_ih + b_hh   (tensor-core mma, split-K KC=4)
    gemm_mma<NGATE, H128, 4><<<dim3(NGATE / 64, 4), 128>>>((const __half*)pz16, wih, part);
    reduce_k<NGATE, 4, false, true><<<(64 * NGATE + 255) / 256, 256>>>(part, bih, bhh, (float*)pgi);

    lstm_kernel<<<ncta, 1024, LSTM_SMEM>>>(whh, out, ncta);
}

// round 15
// speedup vs baseline: 1.0927x; 1.0097x over previous
#include <cuda_runtime.h>
#include <cuda_fp16.h>
#include <cstdint>
#include <math.h>

// ---------------- problem dims ----------------
#define BB    64
#define NN    1024
#define H16   256
#define H64   1024
#define H128  2048
#define NGATE 8192

#define NCTA_MAX 148
#define WROWS 55                                 // gate rows resident in SMEM per CTA
// dynamic SMEM layout for lstm kernel
#define OFF_H16   (WROWS * 2048 * 2)             // 225280: fp16 h copy (4096 B)
#define OFF_G     (OFF_H16 + H128 * 2)           // gate preacts  (256 B)
#define OFF_C     (OFF_G + 64 * 4)               // cell state    (64 B)
#define LSTM_SMEM (OFF_C + 64)                   // 229696 B (<= 232448 max)

// ---------------- device scratch ----------------
__device__ __align__(16) float  g_x [BB * NN];
__device__ __align__(16) float  g_af[BB * H16];
__device__ __align__(16) float  g_ai[BB * H64];
__device__ __align__(16) __half g_z16[BB * H128];
__device__ __align__(16) float  g_gi[BB * NGATE];
__device__ __align__(16) float  g_part[1 << 21];     // split-K partials (8MB)
__device__ __align__(16) __half g_h16[2][H128];      // fp16 recurrent h (double-buffered)
__device__ unsigned g_slot[NCTA_MAX * 8];            // spread barrier slots (32B apart)

// ---------------- release/acquire helpers ----------------
__device__ __forceinline__ void st_release(unsigned* p, unsigned v) {
    asm volatile("st.release.gpu.global.u32 [%0], %1;" :: "l"(p), "r"(v) : "memory");
}
__device__ __forceinline__ unsigned ld_acquire(const unsigned* p) {
    unsigned v;
    asm volatile("ld.acquire.gpu.global.u32 %0, [%1];" : "=r"(v) : "l"(p) : "memory");
    return v;
}

// ---------------- GCN: one block per sample (block 0 also resets barrier slots) ----------------
__global__ __launch_bounds__(1024) void gcn_kernel(
    const float* __restrict__ inp,
    const float* __restrict__ gc1w, const float* __restrict__ gc1b,
    const float* __restrict__ gc2w, const float* __restrict__ gc2b)
{
    __shared__ float xs[NN];
    __shared__ float s2[NN];
    const int s = blockIdx.x;
    const int i = threadIdx.x;
    if (s == 0 && i < NCTA_MAX * 8) g_slot[i] = 0u;   // fold reset here (lstm runs later)
    xs[i] = inp[s * NN + i];
    __syncthreads();
    const float xi = xs[i];

    float d0 = INFINITY, d1 = INFINITY, d2 = INFINITY, d3 = INFINITY;
    int i0 = 0, i1 = 0, i2 = 0, i3 = 0;
#pragma unroll 4
    for (int j = 0; j < NN; ++j) {
        float dj = fabsf(xi - xs[j]);
        if (j != i && dj < d3) {
            if (dj < d2) {
                d3 = d2; i3 = i2;
                if (dj < d1) {
                    d2 = d1; i2 = i1;
                    if (dj < d0) { d1 = d0; i1 = i0; d0 = dj; i0 = j; }
                    else         { d1 = dj; i1 = j; }
                } else { d2 = dj; i2 = j; }
            } else { d3 = dj; i3 = j; }
        }
    }

    float S = xs[i0] + xs[i1] + xs[i2] + xs[i3];
    float v = 0.f;
#pragma unroll
    for (int c = 0; c < 4; ++c) {
        float hc = fmaxf(gc1w[c] * S + gc1b[c], 0.f);
        v += hc * gc2w[c];
    }
    s2[i] = v;
    __syncthreads();
    g_x[s * NN + i] = s2[i0] + s2[i1] + s2[i2] + s2[i3] + gc2b[0];
}

// ---------------- small split-K GEMM (64xR', 128 thr) for fl/il ----------------
template <int R, int J, int KC>
__global__ __launch_bounds__(128) void gemm_sk(
    const float* __restrict__ A, const float* __restrict__ W, float* __restrict__ part)
{
    __shared__ float As[64][33];
    __shared__ float Ws[32][33];
    const int JC  = J / KC;
    const int kc  = blockIdx.y;
    const int br0 = blockIdx.x * 32;
    const int tid = threadIdx.x;
    const int tq  = tid & 15;
    const int rq  = tid >> 4;

    float acc[4][4];
#pragma unroll
    for (int a = 0; a < 4; ++a)
#pragma unroll
        for (int b = 0; b < 4; ++b) acc[a][b] = 0.f;

    const int j_end = (kc + 1) * JC;
    for (int j0 = kc * JC; j0 < j_end; j0 += 32) {
        for (int idx = tid; idx < 64 * 32; idx += 128) {
            int row = idx >> 5, col = idx & 31;
            As[row][col] = A[row * J + j0 + col];
        }
        for (int idx = tid; idx < 32 * 32; idx += 128) {
            int row = idx >> 5, col = idx & 31;
            Ws[row][col] = W[(size_t)(br0 + row) * J + j0 + col];
        }
        __syncthreads();
#pragma unroll
        for (int kk = 0; kk < 32; ++kk) {
            float av[4], wv[4];
#pragma unroll
            for (int a = 0; a < 4; ++a) av[a] = As[tq + 16 * a][kk];
#pragma unroll
            for (int b = 0; b < 4; ++b) wv[b] = Ws[rq + 8 * b][kk];
#pragma unroll
            for (int a = 0; a < 4; ++a)
#pragma unroll
                for (int b = 0; b < 4; ++b) acc[a][b] += av[a] * wv[b];
        }
        __syncthreads();
    }
#pragma unroll
    for (int a = 0; a < 4; ++a)
#pragma unroll
        for (int b = 0; b < 4; ++b)
            part[(size_t)kc * 64 * R + (tq + 16 * a) * R + br0 + rq + 8 * b] = acc[a][b];
}

// ---------------- big split-K fp32 GEMM (ol layer): 64x64 tile, double-buffered ----------------
template <int R, int J, int KC>
__global__ __launch_bounds__(256) void gemm64(
    const float* __restrict__ A, const float* __restrict__ W, float* __restrict__ part)
{
    __shared__ float As[2][64][33];
    __shared__ float Ws[2][64][33];
    const int JC  = J / KC;
    const int kc  = blockIdx.y;
    const int br0 = blockIdx.x * 64;
    const int tid = threadIdx.x;
    const int tq  = tid & 15;
    const int rq  = tid >> 4;

    float acc[4][4];
#pragma unroll
    for (int a = 0; a < 4; ++a)
#pragma unroll
        for (int b = 0; b < 4; ++b) acc[a][b] = 0.f;

    const int jbeg = kc * JC;
    const int nit  = JC / 32;

    auto load = [&](int s, int j0) {
#pragma unroll
        for (int idx = tid; idx < 64 * 32; idx += 256) {
            int row = idx >> 5, col = idx & 31;
            As[s][row][col] = A[row * J + j0 + col];
            Ws[s][row][col] = W[(size_t)(br0 + row) * J + j0 + col];
        }
    };

    load(0, jbeg);
    __syncthreads();
    for (int it = 0; it < nit; ++it) {
        int s = it & 1;
        if (it + 1 < nit) load(s ^ 1, jbeg + (it + 1) * 32);
#pragma unroll
        for (int kk = 0; kk < 32; ++kk) {
            float av[4], wv[4];
#pragma unroll
            for (int a = 0; a < 4; ++a) av[a] = As[s][tq + 16 * a][kk];
#pragma unroll
            for (int b = 0; b < 4; ++b) wv[b] = Ws[s][rq + 16 * b][kk];
#pragma unroll
            for (int a = 0; a < 4; ++a)
#pragma unroll
                for (int b = 0; b < 4; ++b) acc[a][b] += av[a] * wv[b];
        }
        __syncthreads();
    }
#pragma unroll
    for (int a = 0; a < 4; ++a)
#pragma unroll
        for (int b = 0; b < 4; ++b)
            part[(size_t)kc * 64 * R + (tq + 16 * a) * R + br0 + rq + 16 * b] = acc[a][b];
}

// ---------------- gate GEMM: tensor-core mma.sync m16n8k16 ----------------
// part[kc][t][r] = sum_{j in chunk} z16[t][j] * half(w_ih[r][j]); fp32 mma accumulation.
template <int R, int J, int KC>
__global__ __launch_bounds__(128) void gemm_mma(
    const __half* __restrict__ A16, const float* __restrict__ W,
    float* __restrict__ part)
{
    constexpr int LDA = 72;                     // halfs per SMEM row (64 + 8 pad)
    __shared__ __half Asm[2][64 * LDA];
    __shared__ __half Bsm[2][64 * LDA];
    const int JC  = J / KC;                     // 512
    const int kc  = blockIdx.y;
    const int br0 = blockIdx.x * 64;
    const int tid = threadIdx.x;
    const int warp = tid >> 5, lane = tid & 31;
    const int nit = JC / 64;                    // 8 chunks of K=64

    float acc[8][4];
#pragma unroll
    for (int nf = 0; nf < 8; ++nf)
#pragma unroll
        for (int q = 0; q < 4; ++q) acc[nf][q] = 0.f;

    const int lrow = tid >> 1;                  // 0..63
    const int lcol = (tid & 1) * 32;            // half-row split

    auto loadA = [&](int s, int j0) {
        const uint4* src = (const uint4*)(A16 + lrow * J + j0 + lcol);
        uint4* dst = (uint4*)(Asm[s] + lrow * LDA + lcol);
#pragma unroll
        for (int q = 0; q < 4; ++q) dst[q] = src[q];
    };
    auto loadB = [&](int s, int j0) {
        const float4* src = (const float4*)(W + (size_t)(br0 + lrow) * J + j0 + lcol);
        __half2* dst = (__half2*)(Bsm[s] + lrow * LDA + lcol);
#pragma unroll
        for (int q = 0; q < 8; ++q) {
            float4 v = src[q];
            dst[2 * q]     = __floats2half2_rn(v.x, v.y);
            dst[2 * q + 1] = __floats2half2_rn(v.z, v.w);
        }
    };

    const int jbeg = kc * JC;
    loadA(0, jbeg); loadB(0, jbeg);
    __syncthreads();

    for (int it = 0; it < nit; ++it) {
        const int s = it & 1;
        if (it + 1 < nit) { loadA(s ^ 1, jbeg + (it + 1) * 64); loadB(s ^ 1, jbeg + (it + 1) * 64); }

        const __half* As = Asm[s];
        const __half* Bs = Bsm[s];
#pragma unroll
        for (int k16 = 0; k16 < 4; ++k16) {
            uint32_t a0, a1, a2, a3;
            {
                const __half* ap = As + (warp * 16 + (lane & 15)) * LDA + k16 * 16 + (lane >> 4) * 8;
                uint32_t addr = (uint32_t)__cvta_generic_to_shared(ap);
                asm volatile("ldmatrix.sync.aligned.m8n8.x4.shared.b16 {%0,%1,%2,%3}, [%4];"
                             : "=r"(a0), "=r"(a1), "=r"(a2), "=r"(a3) : "r"(addr));
            }
#pragma unroll
            for (int ng = 0; ng < 4; ++ng) {
                uint32_t r0, r1, r2, r3;
                const __half* bp = Bs + (ng * 16 + (lane & 15)) * LDA + k16 * 16 + (lane >> 4) * 8;
                uint32_t addr = (uint32_t)__cvta_generic_to_shared(bp);
                asm volatile("ldmatrix.sync.aligned.m8n8.x4.shared.b16 {%0,%1,%2,%3}, [%4];"
                             : "=r"(r0), "=r"(r1), "=r"(r2), "=r"(r3) : "r"(addr));
                float* c0 = acc[2 * ng];
                asm volatile("mma.sync.aligned.m16n8k16.row.col.f32.f16.f16.f32 "
                             "{%0,%1,%2,%3}, {%4,%5,%6,%7}, {%8,%9}, {%0,%1,%2,%3};"
                             : "+f"(c0[0]), "+f"(c0[1]), "+f"(c0[2]), "+f"(c0[3])
                             : "r"(a0), "r"(a1), "r"(a2), "r"(a3), "r"(r0), "r"(r2));
                float* c1 = acc[2 * ng + 1];
                asm volatile("mma.sync.aligned.m16n8k16.row.col.f32.f16.f16.f32 "
                             "{%0,%1,%2,%3}, {%4,%5,%6,%7}, {%8,%9}, {%0,%1,%2,%3};"
                             : "+f"(c1[0]), "+f"(c1[1]), "+f"(c1[2]), "+f"(c1[3])
                             : "r"(a0), "r"(a1), "r"(a2), "r"(a3), "r"(r1), "r"(r3));
            }
        }
        __syncthreads();
    }

    const int m0 = warp * 16 + (lane >> 2);
    const int rb = (lane & 3) * 2;
    float* base = part + (size_t)kc * 64 * R;
#pragma unroll
    for (int nf = 0; nf < 8; ++nf) {
        int r = br0 + nf * 8 + rb;
        *(float2*)&base[(size_t)m0 * R + r]       = make_float2(acc[nf][0], acc[nf][1]);
        *(float2*)&base[(size_t)(m0 + 8) * R + r] = make_float2(acc[nf][2], acc[nf][3]);
    }
}

// ---------------- reduce partials -> fp32 out ----------------
template <int R, int KC, bool RELU, bool HASB2>
__global__ __launch_bounds__(256) void reduce_k(
    const float* __restrict__ part,
    const float* __restrict__ b1, const float* __restrict__ b2,
    float* __restrict__ C)
{
    int i = blockIdx.x * 256 + threadIdx.x;
    if (i >= 64 * R) return;
    int r = i % R;
    float s = 0.f;
#pragma unroll
    for (int kc = 0; kc < KC; ++kc) s += part[(size_t)kc * 64 * R + i];
    s += b1[r];
    if (HASB2) s += b2[r];
    if (RELU) s = fmaxf(s, 0.f);
    C[i] = s;
}

// ---------------- reduce partials -> relu -> fp16 out (ol layer -> z16), half2 stores ----------------
template <int R, int KC>
__global__ __launch_bounds__(256) void reduce_k_h(
    const float* __restrict__ part, const float* __restrict__ b1,
    __half2* __restrict__ C2)
{
    int p = blockIdx.x * 256 + threadIdx.x;      // half2 index
    if (p >= 64 * R / 2) return;
    int i0 = 2 * p;
    int r0 = i0 % R;
    float s0 = 0.f, s1 = 0.f;
#pragma unroll
    for (int kc = 0; kc < KC; ++kc) {
        const float2 v = *(const float2*)&part[(size_t)kc * 64 * R + i0];
        s0 += v.x; s1 += v.y;
    }
    s0 = fmaxf(s0 + b1[r0], 0.f);
    s1 = fmaxf(s1 + b1[r0 + 1], 0.f);
    C2[p] = __floats2half2_rn(s0, s1);
}

__device__ __forceinline__ float sigmoidf_(float x) { return 1.f / (1.f + expf(-x)); }

// ---------------- persistent LSTM: 55 SMEM rows, split-chain HFMA2, lean sync ----------------
__global__ __launch_bounds__(1024, 1) void lstm_kernel(
    const float* __restrict__ w_hh, float* __restrict__ out, int ncta)
{
    extern __shared__ unsigned char sm[];
    __half* w_sm = (__half*)sm;                     // [WROWS][2048] fp16, row = lr
    __half* h16  = (__half*)(sm + OFF_H16);         // [2048]
    float*  gsm  = (float*)(sm + OFF_G);            // [64]
    float*  csm  = (float*)(sm + OFF_C);            // [16]

    const int tid  = threadIdx.x;
    const int bid  = blockIdx.x;
    const int warp = tid >> 5, lane = tid & 31;

    const int base = H128 / ncta;
    const int rem  = H128 - base * ncta;
    const int nu   = (bid < rem) ? base + 1 : base;
    const int u0   = bid * base + min(bid, rem);
    const int nrows = 4 * nu;
    const int wrows = (nrows < WROWS) ? nrows : WROWS;   // rows resident in SMEM

    // prologue: convert resident rows fp32 -> fp16, SMEM row index = lr
    {
        const int tot2 = wrows * 1024;              // half2 count
        __half2* dst = (__half2*)w_sm;
        for (int idx = tid; idx < tot2; idx += 1024) {
            int lr = idx >> 10, c2 = idx & 1023;
            int g = lr / nu, ui = lr - g * nu;
            const float2* src = (const float2*)(w_hh + (size_t)(g * H128 + u0 + ui) * H128);
            float2 v = src[c2];
            dst[idx] = __floats2half2_rn(v.x, v.y);
        }
    }

    // per-warp row assignment: lr = warp + 32*k (cnt uniform per warp)
    int cnt = 0;
    int rowg[2], gsl[2];
    bool insm[2];
    const uint4*  wr16[2];
    const float4* wr32[2];
#pragma unroll
    for (int k = 0; k < 2; ++k) {
        int lr = warp + 32 * k;
        if (lr < nrows) {
            int g = lr / nu, ui = lr - g * nu;
            rowg[cnt] = g * H128 + u0 + ui;
            gsl [cnt] = lr;
            insm[cnt] = (lr < wrows);
            wr16[cnt] = (const uint4*)(w_sm + (size_t)lr * H128);
            wr32[cnt] = (const float4*)(w_hh + (size_t)rowg[cnt] * H128);
            ++cnt;
        }
    }

    if (tid < nu) { csm[tid] = 0.f; g_h16[0][u0 + tid] = __float2half(0.f); }
    __syncthreads();
    if (tid == 0) st_release(&g_slot[bid * 8], 1u);
    if (tid < ncta) { while (ld_acquire(&g_slot[tid * 8]) < 1u) {} }
    __syncthreads();

    for (int t = 0; t < BB; ++t) {
        // broadcast h into SMEM (already fp16 in global)
        if (tid < H128 / 8) {
            uint4 v = __ldcg((const uint4*)g_h16[t & 1] + tid);
            ((uint4*)h16)[tid] = v;
        }
        // prefetch gate-input terms (L2-resident)
        float gi[2] = {0.f, 0.f};
        if (lane == 0) {
#pragma unroll
            for (int k = 0; k < 2; ++k)
                if (k < cnt) gi[k] = g_gi[t * NGATE + rowg[k]];
        }
        __syncthreads();

        float acc[2] = {0.f, 0.f};
        const uint4* h16u = (const uint4*)h16;
#pragma unroll
        for (int ii = 0; ii < 4; ++ii) {
            const int o = lane + 64 * ii;
            uint4 ha = h16u[o], hb = h16u[o + 32];
            const __half2* hpa = (const __half2*)&ha;
            const __half2* hpb = (const __half2*)&hb;
#pragma unroll
            for (int k = 0; k < 2; ++k) {
                if (k >= cnt) break;                 // warp-uniform branch
                __half2 sa, sb;                      // two independent chains (ILP)
                if (insm[k]) {
                    uint4 wa = wr16[k][o], wb = wr16[k][o + 32];
                    const __half2* wpa = (const __half2*)&wa;
                    const __half2* wpb = (const __half2*)&wb;
                    sa = __hmul2(wpa[0], hpa[0]);
                    sb = __hmul2(wpb[0], hpb[0]);
                    sa = __hfma2(wpa[1], hpa[1], sa);
                    sb = __hfma2(wpb[1], hpb[1], sb);
                    sa = __hfma2(wpa[2], hpa[2], sa);
                    sb = __hfma2(wpb[2], hpb[2], sb);
                    sa = __hfma2(wpa[3], hpa[3], sa);
                    sb = __hfma2(wpb[3], hpb[3], sb);
                } else {
                    float4 a0 = __ldg(wr32[k] + 2 * o);
                    float4 a1 = __ldg(wr32[k] + 2 * o + 1);
                    float4 b0 = __ldg(wr32[k] + 2 * (o + 32));
                    float4 b1 = __ldg(wr32[k] + 2 * (o + 32) + 1);
                    sa = __hmul2(__floats2half2_rn(a0.x, a0.y), hpa[0]);
                    sb = __hmul2(__floats2half2_rn(b0.x, b0.y), hpb[0]);
                    sa = __hfma2(__floats2half2_rn(a0.z, a0.w), hpa[1], sa);
                    sb = __hfma2(__floats2half2_rn(b0.z, b0.w), hpb[1], sb);
                    sa = __hfma2(__floats2half2_rn(a1.x, a1.y), hpa[2], sa);
                    sb = __hfma2(__floats2half2_rn(b1.x, b1.y), hpb[2], sb);
                    sa = __hfma2(__floats2half2_rn(a1.z, a1.w), hpa[3], sa);
                    sb = __hfma2(__floats2half2_rn(b1.z, b1.w), hpb[3], sb);
                }
                float2 fa = __half22float2(sa);
                float2 fb = __half22float2(sb);
                acc[k] += (fa.x + fa.y) + (fb.x + fb.y);
            }
        }
#pragma unroll
        for (int k = 0; k < 2; ++k)
#pragma unroll
            for (int o = 16; o > 0; o >>= 1) acc[k] += __shfl_xor_sync(0xffffffffu, acc[k], o);
        if (lane == 0) {
#pragma unroll
            for (int k = 0; k < 2; ++k)
                if (k < cnt) gsm[gsl[k]] = acc[k] + gi[k];
        }
        __syncthreads();

        // warp 0: activation epilogue + h publish + release (no extra CTA barrier)
        if (warp == 0) {
            if (tid < nu) {
                float ig = gsm[tid], fg = gsm[nu + tid], gg = gsm[2 * nu + tid], og = gsm[3 * nu + tid];
                float c = sigmoidf_(fg) * csm[tid] + sigmoidf_(ig) * tanhf(gg);
                float h = sigmoidf_(og) * tanhf(c);
                csm[tid] = c;
                g_h16[(t + 1) & 1][u0 + tid] = __float2half(h);
                out[t * H128 + u0 + tid] = h;
            }
            __syncwarp();
            if (tid == 0) st_release(&g_slot[bid * 8], (unsigned)(t + 2));
        }
        if (tid < ncta) { unsigned tgt = (unsigned)(t + 2); while (ld_acquire(&g_slot[tid * 8]) < tgt) {} }
        __syncthreads();
    }
}

// ---------------- launch ----------------
extern "C" void kernel_launch(void* const* d_in, const int* in_sizes, int n_in,
                              void* d_out, int out_size)
{
    const float* inp  = (const float*)d_in[0];
    const float* gc1w = (const float*)d_in[3];
    const float* gc1b = (const float*)d_in[4];
    const float* gc2w = (const float*)d_in[5];
    const float* gc2b = (const float*)d_in[6];
    const float* flw  = (const float*)d_in[7];
    const float* flb  = (const float*)d_in[8];
    const float* ilw  = (const float*)d_in[9];
    const float* ilb  = (const float*)d_in[10];
    const float* olw  = (const float*)d_in[11];
    const float* olb  = (const float*)d_in[12];
    const float* wih  = (const float*)d_in[13];
    const float* whh  = (const float*)d_in[14];
    const float* bih  = (const float*)d_in[15];
    const float* bhh  = (const float*)d_in[16];
    float* out = (float*)d_out;

    void *px, *paf, *pai, *pz16, *pgi, *ppart;
    cudaGetSymbolAddress(&px,    g_x);
    cudaGetSymbolAddress(&paf,   g_af);
    cudaGetSymbolAddress(&pai,   g_ai);
    cudaGetSymbolAddress(&pz16,  g_z16);
    cudaGetSymbolAddress(&pgi,   g_gi);
    cudaGetSymbolAddress(&ppart, g_part);
    float* part = (float*)ppart;

    int sms = 0;
    cudaDeviceGetAttribute(&sms, cudaDevAttrMultiProcessorCount, 0);
    int ncta = sms;
    if (ncta > NCTA_MAX) ncta = NCTA_MAX;
    if (ncta < 128) ncta = 128;

    cudaFuncSetAttribute(lstm_kernel, cudaFuncAttributeMaxDynamicSharedMemorySize, LSTM_SMEM);

    gcn_kernel<<<BB, NN>>>(inp, gc1w, gc1b, gc2w, gc2b);   // also resets g_slot

    // fl: [64,256] = x @ fl_w.T ; relu          (KC=32, grid 256, 1 j-iter/block)
    gemm_sk<H16, NN, 32><<<dim3(H16 / 32, 32), 128>>>((const float*)px, flw, part);
    reduce_k<H16, 32, true, false><<<(64 * H16 + 255) / 256, 256>>>(part, flb, nullptr, (float*)paf);
    // il: [64,1024] = af @ il_w.T ; relu        (KC=8, grid 256, 1 j-iter/block)
    gemm_sk<H64, H16, 8><<<dim3(H64 / 32, 8), 128>>>((const float*)paf, ilw, part);
    reduce_k<H64, 8, true, false><<<(64 * H64 + 255) / 256, 256>>>(part, ilb, nullptr, (float*)pai);
    // ol: [64,2048] = ai @ ol_w.T ; relu -> z16 (KC=8, grid 256)
    gemm64<H128, H64, 8><<<dim3(H128 / 64, 8), 256>>>((const float*)pai, olw, part);
    reduce_k_h<H128, 8><<<(64 * H128 / 2 + 255) / 256, 256>>>(part, olb, (__half2*)pz16);
    // gate: [64,8192] = z @ w_ih.T + b_ih + b_hh   (tensor-core mma, split-K KC=4)
    gemm_mma<NGATE, H128, 4><<<dim3(NGATE / 64, 4), 128>>>((const __half*)pz16, wih, part);
    reduce_k<NGATE, 4, false, true><<<(64 * NGATE + 255) / 256, 256>>>(part, bih, bhh, (float*)pgi);

    lstm_kernel<<<ncta, 1024, LSTM_SMEM>>>(whh, out, ncta);
}

// round 17
// speedup vs baseline: 1.1303x; 1.0344x over previous
#include <cuda_runtime.h>
#include <cuda_fp16.h>
#include <cstdint>
#include <math.h>

// ---------------- problem dims ----------------
#define BB    64
#define NN    1024
#define H16   256
#define H64   1024
#define H128  2048
#define NGATE 8192

#define NCTA_MAX 148
#define WROWS 55                                 // gate rows resident in SMEM per CTA
// dynamic SMEM layout for lstm kernel
#define OFF_H16   (WROWS * 2048 * 2)             // 225280: fp16 h copy (4096 B)
#define OFF_G     (OFF_H16 + H128 * 2)           // gate preacts  (256 B)
#define OFF_C     (OFF_G + 64 * 4)               // cell state    (64 B)
#define LSTM_SMEM (OFF_C + 64)                   // 229696 B (<= 232448 max)

// ---------------- device scratch ----------------
__device__ __align__(16) float  g_x [BB * NN];
__device__ __align__(16) float  g_af[BB * H16];
__device__ __align__(16) float  g_ai[BB * H64];
__device__ __align__(16) __half g_z16[BB * H128];
__device__ __align__(16) float  g_gi[BB * NGATE];
__device__ __align__(16) float  g_part[1 << 21];     // split-K partials (8MB)
__device__ __align__(16) __half g_h16[2][H128];      // fp16 recurrent h (double-buffered)
__device__ unsigned g_slot[NCTA_MAX * 8];            // spread barrier slots (32B apart)

// ---------------- release/acquire helpers ----------------
__device__ __forceinline__ void st_release(unsigned* p, unsigned v) {
    asm volatile("st.release.gpu.global.u32 [%0], %1;" :: "l"(p), "r"(v) : "memory");
}
__device__ __forceinline__ unsigned ld_acquire(const unsigned* p) {
    unsigned v;
    asm volatile("ld.acquire.gpu.global.u32 %0, [%1];" : "=r"(v) : "l"(p) : "memory");
    return v;
}

// ---------------- fast activations (hardware approx) ----------------
__device__ __forceinline__ float tanh_fast(float x) {
    float y;
    asm("tanh.approx.f32 %0, %1;" : "=f"(y) : "f"(x));
    return y;
}
__device__ __forceinline__ float sigmoid_fast(float x) {
    return 0.5f * tanh_fast(0.5f * x) + 0.5f;
}

// ---------------- GCN: one block per sample (block 0 also resets barrier slots) ----------------
__global__ __launch_bounds__(1024) void gcn_kernel(
    const float* __restrict__ inp,
    const float* __restrict__ gc1w, const float* __restrict__ gc1b,
    const float* __restrict__ gc2w, const float* __restrict__ gc2b)
{
    __shared__ float xs[NN];
    __shared__ float s2[NN];
    const int s = blockIdx.x;
    const int i = threadIdx.x;
    if (s == 0 && i < NCTA_MAX * 8) g_slot[i] = 0u;
    xs[i] = inp[s * NN + i];
    __syncthreads();
    const float xi = xs[i];

    float d0 = INFINITY, d1 = INFINITY, d2 = INFINITY, d3 = INFINITY;
    int i0 = 0, i1 = 0, i2 = 0, i3 = 0;
#pragma unroll 4
    for (int j = 0; j < NN; ++j) {
        float dj = fabsf(xi - xs[j]);
        if (j != i && dj < d3) {
            if (dj < d2) {
                d3 = d2; i3 = i2;
                if (dj < d1) {
                    d2 = d1; i2 = i1;
                    if (dj < d0) { d1 = d0; i1 = i0; d0 = dj; i0 = j; }
                    else         { d1 = dj; i1 = j; }
                } else { d2 = dj; i2 = j; }
            } else { d3 = dj; i3 = j; }
        }
    }

    float S = xs[i0] + xs[i1] + xs[i2] + xs[i3];
    float v = 0.f;
#pragma unroll
    for (int c = 0; c < 4; ++c) {
        float hc = fmaxf(gc1w[c] * S + gc1b[c], 0.f);
        v += hc * gc2w[c];
    }
    s2[i] = v;
    __syncthreads();
    g_x[s * NN + i] = s2[i0] + s2[i1] + s2[i2] + s2[i3] + gc2b[0];
}

// ---------------- small split-K GEMM (64xR', 128 thr) for fl/il ----------------
template <int R, int J, int KC>
__global__ __launch_bounds__(128) void gemm_sk(
    const float* __restrict__ A, const float* __restrict__ W, float* __restrict__ part)
{
    __shared__ float As[64][33];
    __shared__ float Ws[32][33];
    const int JC  = J / KC;
    const int kc  = blockIdx.y;
    const int br0 = blockIdx.x * 32;
    const int tid = threadIdx.x;
    const int tq  = tid & 15;
    const int rq  = tid >> 4;

    float acc[4][4];
#pragma unroll
    for (int a = 0; a < 4; ++a)
#pragma unroll
        for (int b = 0; b < 4; ++b) acc[a][b] = 0.f;

    const int j_end = (kc + 1) * JC;
    for (int j0 = kc * JC; j0 < j_end; j0 += 32) {
        for (int idx = tid; idx < 64 * 32; idx += 128) {
            int row = idx >> 5, col = idx & 31;
            As[row][col] = A[row * J + j0 + col];
        }
        for (int idx = tid; idx < 32 * 32; idx += 128) {
            int row = idx >> 5, col = idx & 31;
            Ws[row][col] = W[(size_t)(br0 + row) * J + j0 + col];
        }
        __syncthreads();
#pragma unroll
        for (int kk = 0; kk < 32; ++kk) {
            float av[4], wv[4];
#pragma unroll
            for (int a = 0; a < 4; ++a) av[a] = As[tq + 16 * a][kk];
#pragma unroll
            for (int b = 0; b < 4; ++b) wv[b] = Ws[rq + 8 * b][kk];
#pragma unroll
            for (int a = 0; a < 4; ++a)
#pragma unroll
                for (int b = 0; b < 4; ++b) acc[a][b] += av[a] * wv[b];
        }
        __syncthreads();
    }
#pragma unroll
    for (int a = 0; a < 4; ++a)
#pragma unroll
        for (int b = 0; b < 4; ++b)
            part[(size_t)kc * 64 * R + (tq + 16 * a) * R + br0 + rq + 8 * b] = acc[a][b];
}

// ---------------- big split-K fp32 GEMM (ol layer): 64x64 tile, double-buffered ----------------
template <int R, int J, int KC>
__global__ __launch_bounds__(256) void gemm64(
    const float* __restrict__ A, const float* __restrict__ W, float* __restrict__ part)
{
    __shared__ float As[2][64][33];
    __shared__ float Ws[2][64][33];
    const int JC  = J / KC;
    const int kc  = blockIdx.y;
    const int br0 = blockIdx.x * 64;
    const int tid = threadIdx.x;
    const int tq  = tid & 15;
    const int rq  = tid >> 4;

    float acc[4][4];
#pragma unroll
    for (int a = 0; a < 4; ++a)
#pragma unroll
        for (int b = 0; b < 4; ++b) acc[a][b] = 0.f;

    const int jbeg = kc * JC;
    const int nit  = JC / 32;

    auto load = [&](int s, int j0) {
#pragma unroll
        for (int idx = tid; idx < 64 * 32; idx += 256) {
            int row = idx >> 5, col = idx & 31;
            As[s][row][col] = A[row * J + j0 + col];
            Ws[s][row][col] = W[(size_t)(br0 + row) * J + j0 + col];
        }
    };

    load(0, jbeg);
    __syncthreads();
    for (int it = 0; it < nit; ++it) {
        int s = it & 1;
        if (it + 1 < nit) load(s ^ 1, jbeg + (it + 1) * 32);
#pragma unroll
        for (int kk = 0; kk < 32; ++kk) {
            float av[4], wv[4];
#pragma unroll
            for (int a = 0; a < 4; ++a) av[a] = As[s][tq + 16 * a][kk];
#pragma unroll
            for (int b = 0; b < 4; ++b) wv[b] = Ws[s][rq + 16 * b][kk];
#pragma unroll
            for (int a = 0; a < 4; ++a)
#pragma unroll
                for (int b = 0; b < 4; ++b) acc[a][b] += av[a] * wv[b];
        }
        __syncthreads();
    }
#pragma unroll
    for (int a = 0; a < 4; ++a)
#pragma unroll
        for (int b = 0; b < 4; ++b)
            part[(size_t)kc * 64 * R + (tq + 16 * a) * R + br0 + rq + 16 * b] = acc[a][b];
}

// ---------------- gate GEMM: tensor-core mma.sync m16n8k16 ----------------
template <int R, int J, int KC>
__global__ __launch_bounds__(128) void gemm_mma(
    const __half* __restrict__ A16, const float* __restrict__ W,
    float* __restrict__ part)
{
    constexpr int LDA = 72;
    __shared__ __half Asm[2][64 * LDA];
    __shared__ __half Bsm[2][64 * LDA];
    const int JC  = J / KC;
    const int kc  = blockIdx.y;
    const int br0 = blockIdx.x * 64;
    const int tid = threadIdx.x;
    const int warp = tid >> 5, lane = tid & 31;
    const int nit = JC / 64;

    float acc[8][4];
#pragma unroll
    for (int nf = 0; nf < 8; ++nf)
#pragma unroll
        for (int q = 0; q < 4; ++q) acc[nf][q] = 0.f;

    const int lrow = tid >> 1;
    const int lcol = (tid & 1) * 32;

    auto loadA = [&](int s, int j0) {
        const uint4* src = (const uint4*)(A16 + lrow * J + j0 + lcol);
        uint4* dst = (uint4*)(Asm[s] + lrow * LDA + lcol);
#pragma unroll
        for (int q = 0; q < 4; ++q) dst[q] = src[q];
    };
    auto loadB = [&](int s, int j0) {
        const float4* src = (const float4*)(W + (size_t)(br0 + lrow) * J + j0 + lcol);
        __half2* dst = (__half2*)(Bsm[s] + lrow * LDA + lcol);
#pragma unroll
        for (int q = 0; q < 8; ++q) {
            float4 v = src[q];
            dst[2 * q]     = __floats2half2_rn(v.x, v.y);
            dst[2 * q + 1] = __floats2half2_rn(v.z, v.w);
        }
    };

    const int jbeg = kc * JC;
    loadA(0, jbeg); loadB(0, jbeg);
    __syncthreads();

    for (int it = 0; it < nit; ++it) {
        const int s = it & 1;
        if (it + 1 < nit) { loadA(s ^ 1, jbeg + (it + 1) * 64); loadB(s ^ 1, jbeg + (it + 1) * 64); }

        const __half* As = Asm[s];
        const __half* Bs = Bsm[s];
#pragma unroll
        for (int k16 = 0; k16 < 4; ++k16) {
            uint32_t a0, a1, a2, a3;
            {
                const __half* ap = As + (warp * 16 + (lane & 15)) * LDA + k16 * 16 + (lane >> 4) * 8;
                uint32_t addr = (uint32_t)__cvta_generic_to_shared(ap);
                asm volatile("ldmatrix.sync.aligned.m8n8.x4.shared.b16 {%0,%1,%2,%3}, [%4];"
                             : "=r"(a0), "=r"(a1), "=r"(a2), "=r"(a3) : "r"(addr));
            }
#pragma unroll
            for (int ng = 0; ng < 4; ++ng) {
                uint32_t r0, r1, r2, r3;
                const __half* bp = Bs + (ng * 16 + (lane & 15)) * LDA + k16 * 16 + (lane >> 4) * 8;
                uint32_t addr = (uint32_t)__cvta_generic_to_shared(bp);
                asm volatile("ldmatrix.sync.aligned.m8n8.x4.shared.b16 {%0,%1,%2,%3}, [%4];"
                             : "=r"(r0), "=r"(r1), "=r"(r2), "=r"(r3) : "r"(addr));
                float* c0 = acc[2 * ng];
                asm volatile("mma.sync.aligned.m16n8k16.row.col.f32.f16.f16.f32 "
                             "{%0,%1,%2,%3}, {%4,%5,%6,%7}, {%8,%9}, {%0,%1,%2,%3};"
                             : "+f"(c0[0]), "+f"(c0[1]), "+f"(c0[2]), "+f"(c0[3])
                             : "r"(a0), "r"(a1), "r"(a2), "r"(a3), "r"(r0), "r"(r2));
                float* c1 = acc[2 * ng + 1];
                asm volatile("mma.sync.aligned.m16n8k16.row.col.f32.f16.f16.f32 "
                             "{%0,%1,%2,%3}, {%4,%5,%6,%7}, {%8,%9}, {%0,%1,%2,%3};"
                             : "+f"(c1[0]), "+f"(c1[1]), "+f"(c1[2]), "+f"(c1[3])
                             : "r"(a0), "r"(a1), "r"(a2), "r"(a3), "r"(r1), "r"(r3));
            }
        }
        __syncthreads();
    }

    const int m0 = warp * 16 + (lane >> 2);
    const int rb = (lane & 3) * 2;
    float* base = part + (size_t)kc * 64 * R;
#pragma unroll
    for (int nf = 0; nf < 8; ++nf) {
        int r = br0 + nf * 8 + rb;
        *(float2*)&base[(size_t)m0 * R + r]       = make_float2(acc[nf][0], acc[nf][1]);
        *(float2*)&base[(size_t)(m0 + 8) * R + r] = make_float2(acc[nf][2], acc[nf][3]);
    }
}

// ---------------- reduce partials -> fp32 out ----------------
template <int R, int KC, bool RELU, bool HASB2>
__global__ __launch_bounds__(256) void reduce_k(
    const float* __restrict__ part,
    const float* __restrict__ b1, const float* __restrict__ b2,
    float* __restrict__ C)
{
    int i = blockIdx.x * 256 + threadIdx.x;
    if (i >= 64 * R) return;
    int r = i % R;
    float s = 0.f;
#pragma unroll
    for (int kc = 0; kc < KC; ++kc) s += part[(size_t)kc * 64 * R + i];
    s += b1[r];
    if (HASB2) s += b2[r];
    if (RELU) s = fmaxf(s, 0.f);
    C[i] = s;
}

// ---------------- reduce partials -> relu -> fp16 out (ol layer -> z16), half2 stores ----------------
template <int R, int KC>
__global__ __launch_bounds__(256) void reduce_k_h(
    const float* __restrict__ part, const float* __restrict__ b1,
    __half2* __restrict__ C2)
{
    int p = blockIdx.x * 256 + threadIdx.x;
    if (p >= 64 * R / 2) return;
    int i0 = 2 * p;
    int r0 = i0 % R;
    float s0 = 0.f, s1 = 0.f;
#pragma unroll
    for (int kc = 0; kc < KC; ++kc) {
        const float2 v = *(const float2*)&part[(size_t)kc * 64 * R + i0];
        s0 += v.x; s1 += v.y;
    }
    s0 = fmaxf(s0 + b1[r0], 0.f);
    s1 = fmaxf(s1 + b1[r0 + 1], 0.f);
    C2[p] = __floats2half2_rn(s0, s1);
}

// ---------------- persistent LSTM: 55 SMEM rows, split-chain HFMA2, fast epilogue ----------------
__global__ __launch_bounds__(1024, 1) void lstm_kernel(
    const float* __restrict__ w_hh, float* __restrict__ out, int ncta)
{
    extern __shared__ unsigned char sm[];
    __half* w_sm = (__half*)sm;                     // [WROWS][2048] fp16, row = lr
    __half* h16  = (__half*)(sm + OFF_H16);         // [2048]
    float*  gsm  = (float*)(sm + OFF_G);            // [64]
    float*  csm  = (float*)(sm + OFF_C);            // [16]

    const int tid  = threadIdx.x;
    const int bid  = blockIdx.x;
    const int warp = tid >> 5, lane = tid & 31;

    const int base = H128 / ncta;
    const int rem  = H128 - base * ncta;
    const int nu   = (bid < rem) ? base + 1 : base;
    const int u0   = bid * base + min(bid, rem);
    const int nrows = 4 * nu;
    const int wrows = (nrows < WROWS) ? nrows : WROWS;

    // prologue: convert resident rows fp32 -> fp16, SMEM row index = lr
    {
        const int tot2 = wrows * 1024;
        __half2* dst = (__half2*)w_sm;
        for (int idx = tid; idx < tot2; idx += 1024) {
            int lr = idx >> 10, c2 = idx & 1023;
            int g = lr / nu, ui = lr - g * nu;
            const float2* src = (const float2*)(w_hh + (size_t)(g * H128 + u0 + ui) * H128);
            float2 v = src[c2];
            dst[idx] = __floats2half2_rn(v.x, v.y);
        }
    }

    // per-warp row assignment: lr = warp + 32*k (cnt uniform per warp)
    int cnt = 0;
    int rowg[2], gsl[2];
    bool insm[2];
    const uint4*  wr16[2];
    const float4* wr32[2];
#pragma unroll
    for (int k = 0; k < 2; ++k) {
        int lr = warp + 32 * k;
        if (lr < nrows) {
            int g = lr / nu, ui = lr - g * nu;
            rowg[cnt] = g * H128 + u0 + ui;
            gsl [cnt] = lr;
            insm[cnt] = (lr < wrows);
            wr16[cnt] = (const uint4*)(w_sm + (size_t)lr * H128);
            wr32[cnt] = (const float4*)(w_hh + (size_t)rowg[cnt] * H128);
            ++cnt;
        }
    }

    if (tid < nu) { csm[tid] = 0.f; g_h16[0][u0 + tid] = __float2half(0.f); }
    __syncthreads();
    if (tid == 0) st_release(&g_slot[bid * 8], 1u);
    if (tid < ncta) { while (ld_acquire(&g_slot[tid * 8]) < 1u) {} }
    __syncthreads();

    for (int t = 0; t < BB; ++t) {
        if (tid < H128 / 8) {
            uint4 v = __ldcg((const uint4*)g_h16[t & 1] + tid);
            ((uint4*)h16)[tid] = v;
        }
        float gi[2] = {0.f, 0.f};
        if (lane == 0) {
#pragma unroll
            for (int k = 0; k < 2; ++k)
                if (k < cnt) gi[k] = g_gi[t * NGATE + rowg[k]];
        }
        __syncthreads();

        float acc[2] = {0.f, 0.f};
        const uint4* h16u = (const uint4*)h16;
#pragma unroll
        for (int ii = 0; ii < 4; ++ii) {
            const int o = lane + 64 * ii;
            uint4 ha = h16u[o], hb = h16u[o + 32];
            const __half2* hpa = (const __half2*)&ha;
            const __half2* hpb = (const __half2*)&hb;
#pragma unroll
            for (int k = 0; k < 2; ++k) {
                if (k >= cnt) break;
                __half2 sa, sb;
                if (insm[k]) {
                    uint4 wa = wr16[k][o], wb = wr16[k][o + 32];
                    const __half2* wpa = (const __half2*)&wa;
                    const __half2* wpb = (const __half2*)&wb;
                    sa = __hmul2(wpa[0], hpa[0]);
                    sb = __hmul2(wpb[0], hpb[0]);
                    sa = __hfma2(wpa[1], hpa[1], sa);
                    sb = __hfma2(wpb[1], hpb[1], sb);
                    sa = __hfma2(wpa[2], hpa[2], sa);
                    sb = __hfma2(wpb[2], hpb[2], sb);
                    sa = __hfma2(wpa[3], hpa[3], sa);
                    sb = __hfma2(wpb[3], hpb[3], sb);
                } else {
                    float4 a0 = __ldg(wr32[k] + 2 * o);
                    float4 a1 = __ldg(wr32[k] + 2 * o + 1);
                    float4 b0 = __ldg(wr32[k] + 2 * (o + 32));
                    float4 b1 = __ldg(wr32[k] + 2 * (o + 32) + 1);
                    sa = __hmul2(__floats2half2_rn(a0.x, a0.y), hpa[0]);
                    sb = __hmul2(__floats2half2_rn(b0.x, b0.y), hpb[0]);
                    sa = __hfma2(__floats2half2_rn(a0.z, a0.w), hpa[1], sa);
                    sb = __hfma2(__floats2half2_rn(b0.z, b0.w), hpb[1], sb);
                    sa = __hfma2(__floats2half2_rn(a1.x, a1.y), hpa[2], sa);
                    sb = __hfma2(__floats2half2_rn(b1.x, b1.y), hpb[2], sb);
                    sa = __hfma2(__floats2half2_rn(a1.z, a1.w), hpa[3], sa);
                    sb = __hfma2(__floats2half2_rn(b1.z, b1.w), hpb[3], sb);
                }
                float2 fa = __half22float2(sa);
                float2 fb = __half22float2(sb);
                acc[k] += (fa.x + fa.y) + (fb.x + fb.y);
            }
        }
#pragma unroll
        for (int k = 0; k < 2; ++k)
#pragma unroll
            for (int o = 16; o > 0; o >>= 1) acc[k] += __shfl_xor_sync(0xffffffffu, acc[k], o);
        if (lane == 0) {
#pragma unroll
            for (int k = 0; k < 2; ++k)
                if (k < cnt) gsm[gsl[k]] = acc[k] + gi[k];
        }
        __syncthreads();

        // warp 0: fast-approx activation epilogue; h publish + release FIRST, out store after
        if (warp == 0) {
            float h = 0.f, c = 0.f;
            if (tid < nu) {
                float ig = gsm[tid], fg = gsm[nu + tid], gg = gsm[2 * nu + tid], og = gsm[3 * nu + tid];
                c = sigmoid_fast(fg) * csm[tid] + sigmoid_fast(ig) * tanh_fast(gg);
                h = sigmoid_fast(og) * tanh_fast(c);
                csm[tid] = c;
                g_h16[(t + 1) & 1][u0 + tid] = __float2half(h);
            }
            __syncwarp();
            if (tid == 0) st_release(&g_slot[bid * 8], (unsigned)(t + 2));
            if (tid < nu) out[t * H128 + u0 + tid] = h;   // off the critical path
        }
        if (tid < ncta) { unsigned tgt = (unsigned)(t + 2); while (ld_acquire(&g_slot[tid * 8]) < tgt) {} }
        __syncthreads();
    }
}

// ---------------- launch ----------------
extern "C" void kernel_launch(void* const* d_in, const int* in_sizes, int n_in,
                              void* d_out, int out_size)
{
    const float* inp  = (const float*)d_in[0];
    const float* gc1w = (const float*)d_in[3];
    const float* gc1b = (const float*)d_in[4];
    const float* gc2w = (const float*)d_in[5];
    const float* gc2b = (const float*)d_in[6];
    const float* flw  = (const float*)d_in[7];
    const float* flb  = (const float*)d_in[8];
    const float* ilw  = (const float*)d_in[9];
    const float* ilb  = (const float*)d_in[10];
    const float* olw  = (const float*)d_in[11];
    const float* olb  = (const float*)d_in[12];
    const float* wih  = (const float*)d_in[13];
    const float* whh  = (const float*)d_in[14];
    const float* bih  = (const float*)d_in[15];
    const float* bhh  = (const float*)d_in[16];
    float* out = (float*)d_out;

    void *px, *paf, *pai, *pz16, *pgi, *ppart;
    cudaGetSymbolAddress(&px,    g_x);
    cudaGetSymbolAddress(&paf,   g_af);
    cudaGetSymbolAddress(&pai,   g_ai);
    cudaGetSymbolAddress(&pz16,  g_z16);
    cudaGetSymbolAddress(&pgi,   g_gi);
    cudaGetSymbolAddress(&ppart, g_part);
    float* part = (float*)ppart;

    int sms = 0;
    cudaDeviceGetAttribute(&sms, cudaDevAttrMultiProcessorCount, 0);
    int ncta = sms;
    if (ncta > NCTA_MAX) ncta = NCTA_MAX;
    if (ncta < 128) ncta = 128;

    cudaFuncSetAttribute(lstm_kernel, cudaFuncAttributeMaxDynamicSharedMemorySize, LSTM_SMEM);

    gcn_kernel<<<BB, NN>>>(inp, gc1w, gc1b, gc2w, gc2b);   // also resets g_slot

    // fl: [64,256] = x @ fl_w.T ; relu          (KC=32, grid 256)
    gemm_sk<H16, NN, 32><<<dim3(H16 / 32, 32), 128>>>((const float*)px, flw, part);
    reduce_k<H16, 32, true, false><<<(64 * H16 + 255) / 256, 256>>>(part, flb, nullptr, (float*)paf);
    // il: [64,1024] = af @ il_w.T ; relu        (KC=8, grid 256)
    gemm_sk<H64, H16, 8><<<dim3(H64 / 32, 8), 128>>>((const float*)paf, ilw, part);
    reduce_k<H64, 8, true, false><<<(64 * H64 + 255) / 256, 256>>>(part, ilb, nullptr, (float*)pai);
    // ol: [64,2048] = ai @ ol_w.T ; relu -> z16 (KC=8, grid 256)
    gemm64<H128, H64, 8><<<dim3(H128 / 64, 8), 256>>>((const float*)pai, olw, part);
    reduce_k_h<H128, 8><<<(64 * H128 / 2 + 255) / 256, 256>>>(part, olb, (__half2*)pz16);
    // gate: [64,8192] = z @ w_ih.T + b_ih + b_hh   (tensor-core mma, split-K KC=4)
    gemm_mma<NGATE, H128, 4><<<dim3(NGATE / 64, 4), 128>>>((const __half*)pz16, wih, part);
    reduce_k<NGATE, 4, false, true><<<(64 * NGATE + 255) / 256, 256>>>(part, bih, bhh, (float*)pgi);

    lstm_kernel<<<ncta, 1024, LSTM_SMEM>>>(whh, out, ncta);
}